// round 12
// baseline (speedup 1.0000x reference)
#include <cuda_runtime.h>
#include <cuda_bf16.h>
#include <math.h>

#define NB    256
#define NM    6
#define INC   448
#define EMB   32
#define OBS   20
#define HOR   30
#define DD    512
#define DFF   2048
#define BMT   1536     // NB*NM
#define NGRP  3
#define GROWS (BMT / NGRP)   // 512 rows per group

// ------------------------- scratch (static device globals) -------------------------
__device__ __align__(256) float g_cfeat[NB*1536];
__device__ __align__(256) float g_cffus[NB*448];
__device__ __align__(256) float g_Wcat[64*2560];       // tf32; cols 1536:2560 = emb->eKV map
__device__ __align__(256) float g_Wor[512*512];
__device__ __align__(256) float g_Wff1r[512*2048];
__device__ __align__(256) float g_Wff2r[2048*512];
__device__ __align__(256) float g_Wfusr[512*448];
__device__ __align__(256) float g_eobs[OBS*NB*32];     // rows ordered [b][l]
__device__ __align__(256) __nv_bfloat16 g_eKVo[(size_t)NB*OBS*1024];   // [b][l][1024]
__device__ __align__(256) __nv_bfloat16 g_eKV[(size_t)BMT*HOR*1024];   // [bm][slot][1024]
__device__ __align__(256) float g_E[BMT*64];
__device__ __align__(256) float g_xlast[BMT*DD];
__device__ __align__(256) float g_rowfus[BMT*448];
__device__ __align__(256) float g_QKVC[BMT*1536];
__device__ __align__(256) float g_ctx[BMT*DD];
__device__ __align__(256) float g_h1[BMT*DD];
__device__ __align__(256) float g_ff1[BMT*DFF];
__device__ __align__(256) float g_h2[BMT*DD];

// --------------------------- TF32 helpers ----------------------------------------
__device__ __forceinline__ unsigned f2tf(float x) {
    unsigned u;
    asm("cvt.rna.tf32.f32 %0, %1;" : "=r"(u) : "f"(x));
    return u;
}
__device__ __forceinline__ float tfr(float x) { return __uint_as_float(f2tf(x)); }

__device__ __forceinline__ void mma8(float* d, const unsigned* a, const unsigned* b) {
    asm volatile(
        "mma.sync.aligned.m16n8k8.row.col.f32.tf32.tf32.f32 "
        "{%0,%1,%2,%3}, {%4,%5,%6,%7}, {%8,%9}, {%0,%1,%2,%3};"
        : "+f"(d[0]), "+f"(d[1]), "+f"(d[2]), "+f"(d[3])
        : "r"(a[0]), "r"(a[1]), "r"(a[2]), "r"(a[3]), "r"(b[0]), "r"(b[1]));
}

// ============ TF32 GEMM: 64x64 tile, 3-stage cp.async (tf32-pre-rounded) ==========
// EK != null: blocks with col0 >= ekcol write bf16 to EK[r*ekld + ekoff + (c-ekcol)].
__global__ void k_gemmt(const float* __restrict__ A, int lda,
                        const float* __restrict__ Bm, int ldb,
                        float* __restrict__ C, int ldc, int K,
                        const float* __restrict__ bias,
                        const float* __restrict__ rowadd, int ramod, int ldra,
                        int relu, int otf32,
                        __nv_bfloat16* __restrict__ EK, int ekcol, int ekoff, int ekld)
{
    const int BPAD = 68, ASZ = 64 * 36, BSZ = 32 * BPAD;
    extern __shared__ float sm[];
    float* AsB = sm;            // 3 stages
    float* BsB = sm + 3 * ASZ;

    const int row0 = blockIdx.y * 64, col0 = blockIdx.x * 64;
    const int tid = threadIdx.x, warp = tid >> 5, lane = tid & 31;
    const int wm = warp >> 2, wn = warp & 3;
    const int l4 = lane >> 2, lm4 = lane & 3;
    const int ar = tid >> 3, akq = (tid & 7) * 4;
    const int brow0 = tid >> 4, bc4 = (tid & 15) * 4;

    float acc[2][2][4] = {};

    auto load = [&](int k0, int s) {
        float* as = AsB + s * ASZ;
        float* bs = BsB + s * BSZ;
#pragma unroll
        for (int i = 0; i < 2; i++) {
            unsigned d = (unsigned)__cvta_generic_to_shared(as + (ar + i * 32) * 36 + akq);
            const float* g = A + (size_t)(row0 + ar + i * 32) * lda + k0 + akq;
            asm volatile("cp.async.cg.shared.global [%0],[%1],16;\n" :: "r"(d), "l"(g));
        }
#pragma unroll
        for (int i = 0; i < 2; i++) {
            int row = brow0 + i * 16;
            unsigned d = (unsigned)__cvta_generic_to_shared(bs + row * BPAD + bc4);
            const float* g = Bm + (size_t)(k0 + row) * ldb + col0 + bc4;
            asm volatile("cp.async.cg.shared.global [%0],[%1],16;\n" :: "r"(d), "l"(g));
        }
        asm volatile("cp.async.commit_group;\n");
    };

    const int nslab = K >> 5;
    load(0, 0);
    if (nslab > 1) load(32, 1); else asm volatile("cp.async.commit_group;\n");

    for (int k = 0; k < nslab; k++) {
        asm volatile("cp.async.wait_group 1;\n");
        __syncthreads();
        if (k + 2 < nslab) load((k + 2) * 32, (k + 2) % 3);
        else               asm volatile("cp.async.commit_group;\n");
        const float* as = AsB + (k % 3) * ASZ;
        const float* bs = BsB + (k % 3) * BSZ;
#pragma unroll
        for (int ks = 0; ks < 4; ks++) {
            const int kk = ks * 8;
            unsigned a[2][4], b[2][2];
#pragma unroll
            for (int mi = 0; mi < 2; mi++) {
                int mb = wm * 32 + mi * 16 + l4;
                a[mi][0] = __float_as_uint(as[mb * 36 + kk + lm4]);
                a[mi][1] = __float_as_uint(as[(mb + 8) * 36 + kk + lm4]);
                a[mi][2] = __float_as_uint(as[mb * 36 + kk + lm4 + 4]);
                a[mi][3] = __float_as_uint(as[(mb + 8) * 36 + kk + lm4 + 4]);
            }
#pragma unroll
            for (int nj = 0; nj < 2; nj++) {
                int nb = wn * 16 + nj * 8 + l4;
                b[nj][0] = __float_as_uint(bs[(kk + lm4) * BPAD + nb]);
                b[nj][1] = __float_as_uint(bs[(kk + lm4 + 4) * BPAD + nb]);
            }
#pragma unroll
            for (int mi = 0; mi < 2; mi++)
#pragma unroll
                for (int nj = 0; nj < 2; nj++)
                    mma8(acc[mi][nj], a[mi], b[nj]);
        }
        __syncthreads();
    }

    const bool ekreg = (EK != 0) && (col0 >= ekcol);
#pragma unroll
    for (int mi = 0; mi < 2; mi++) {
        const int rb = row0 + wm * 32 + mi * 16 + l4;
#pragma unroll
        for (int nj = 0; nj < 2; nj++) {
            const int c = col0 + wn * 16 + nj * 8 + lm4 * 2;
#pragma unroll
            for (int h = 0; h < 2; h++) {
                const int r = rb + h * 8;
                float v0 = acc[mi][nj][h * 2 + 0];
                float v1 = acc[mi][nj][h * 2 + 1];
                if (ekreg) {
                    *(__nv_bfloat162*)(EK + (size_t)r * ekld + ekoff + (c - ekcol)) =
                        __floats2bfloat162_rn(v0, v1);
                    continue;
                }
                if (bias) { v0 += bias[c]; v1 += bias[c + 1]; }
                if (rowadd) {
                    const float* ra = rowadd + (size_t)(r % ramod) * ldra + c;
                    v0 += ra[0]; v1 += ra[1];
                }
                if (relu) { v0 = fmaxf(v0, 0.f); v1 = fmaxf(v1, 0.f); }
                if (otf32) { v0 = tfr(v0); v1 = tfr(v1); }
                *(float2*)(C + (size_t)r * ldc + c) = make_float2(v0, v1);
            }
        }
    }
}

// ===== fused row-block GEMM(512 cols) + LN: out = tf32(LN(A@W + bias + add)) ======
// 32 rows/block, N=512, 8 warps x 64 cols, 2-stage cp.async, K % 32 == 0.
#define BPN 516
__global__ void k_rowln(const float* __restrict__ A, int lda, int K,
                        const float* __restrict__ W,
                        const float* __restrict__ bias,
                        const float* __restrict__ add,
                        const float* __restrict__ gg, const float* __restrict__ bb,
                        float* __restrict__ out)
{
    extern __shared__ float sm[];
    const int ASZ = 32 * 36, BSZ = 32 * BPN;
    float* Ast = sm;                 // 2 stages
    float* Bst = sm + 2 * ASZ;       // 2 stages
    float* rb  = sm + 2 * ASZ + 2 * BSZ;   // 32 x BPN

    const int rows0 = blockIdx.x * 32;
    const int tid = threadIdx.x, w = tid >> 5, lane = tid & 31;
    const int l4 = lane >> 2, lm4 = lane & 3;
    const int ar = tid >> 3, akq = (tid & 7) * 4;

    float acc[2][8][4] = {};

    auto load = [&](int k0, int s) {
        float* as = Ast + s * ASZ;
        float* bs = Bst + s * BSZ;
        {
            unsigned d = (unsigned)__cvta_generic_to_shared(as + ar * 36 + akq);
            const float* g = A + (size_t)(rows0 + ar) * lda + k0 + akq;
            asm volatile("cp.async.cg.shared.global [%0],[%1],16;\n" :: "r"(d), "l"(g));
        }
#pragma unroll
        for (int j = 0; j < 16; j++) {
            int id = tid + j * 256;
            int brow = id >> 7, bc4 = (id & 127) * 4;
            unsigned d = (unsigned)__cvta_generic_to_shared(bs + brow * BPN + bc4);
            const float* g = W + (size_t)(k0 + brow) * 512 + bc4;
            asm volatile("cp.async.cg.shared.global [%0],[%1],16;\n" :: "r"(d), "l"(g));
        }
        asm volatile("cp.async.commit_group;\n");
    };

    const int nslab = K >> 5;
    load(0, 0);
    if (nslab > 1) load(32, 1); else asm volatile("cp.async.commit_group;\n");

    for (int k = 0; k < nslab; k++) {
        asm volatile("cp.async.wait_group 1;\n");
        __syncthreads();
        const float* as = Ast + (k & 1) * ASZ;
        const float* bs = Bst + (k & 1) * BSZ;
#pragma unroll
        for (int ks = 0; ks < 4; ks++) {
            const int kk = ks * 8;
            unsigned a[2][4], b[8][2];
#pragma unroll
            for (int mi = 0; mi < 2; mi++) {
                int mb = mi * 16 + l4;
                a[mi][0] = __float_as_uint(as[mb * 36 + kk + lm4]);
                a[mi][1] = __float_as_uint(as[(mb + 8) * 36 + kk + lm4]);
                a[mi][2] = __float_as_uint(as[mb * 36 + kk + lm4 + 4]);
                a[mi][3] = __float_as_uint(as[(mb + 8) * 36 + kk + lm4 + 4]);
            }
#pragma unroll
            for (int nj = 0; nj < 8; nj++) {
                int nb = w * 64 + nj * 8 + l4;
                b[nj][0] = __float_as_uint(bs[(kk + lm4) * BPN + nb]);
                b[nj][1] = __float_as_uint(bs[(kk + lm4 + 4) * BPN + nb]);
            }
#pragma unroll
            for (int mi = 0; mi < 2; mi++)
#pragma unroll
                for (int nj = 0; nj < 8; nj++)
                    mma8(acc[mi][nj], a[mi], b[nj]);
        }
        __syncthreads();
        if (k + 2 < nslab) load((k + 2) * 32, k & 1);
        else               asm volatile("cp.async.commit_group;\n");
    }

    // write rows to smem with bias + add
#pragma unroll
    for (int mi = 0; mi < 2; mi++)
#pragma unroll
        for (int nj = 0; nj < 8; nj++)
#pragma unroll
            for (int h = 0; h < 2; h++) {
                int r = mi * 16 + l4 + h * 8;
                int c = w * 64 + nj * 8 + lm4 * 2;
                float v0 = acc[mi][nj][h * 2 + 0] + bias[c]
                         + add[(size_t)(rows0 + r) * 512 + c];
                float v1 = acc[mi][nj][h * 2 + 1] + bias[c + 1]
                         + add[(size_t)(rows0 + r) * 512 + c + 1];
                rb[r * BPN + c]     = v0;
                rb[r * BPN + c + 1] = v1;
            }
    __syncthreads();

    // LN: warp w handles rows 4w .. 4w+3
#pragma unroll
    for (int rr = 0; rr < 4; rr++) {
        int row = w * 4 + rr;
        float v[16];
        float sum = 0.f;
#pragma unroll
        for (int j = 0; j < 16; j++) { v[j] = rb[row * BPN + lane + j * 32]; sum += v[j]; }
#pragma unroll
        for (int o = 16; o; o >>= 1) sum += __shfl_xor_sync(0xffffffffu, sum, o);
        float mu = sum * (1.f / 512.f);
        float var = 0.f;
#pragma unroll
        for (int j = 0; j < 16; j++) { float d = v[j] - mu; var += d * d; }
#pragma unroll
        for (int o = 16; o; o >>= 1) var += __shfl_xor_sync(0xffffffffu, var, o);
        float rs = rsqrtf(var * (1.f / 512.f) + 1e-5f);
#pragma unroll
        for (int j = 0; j < 16; j++) {
            int e = lane + j * 32;
            out[(size_t)(rows0 + row) * 512 + e] = tfr((v[j] - mu) * rs * gg[e] + bb[e]);
        }
    }
}

// ===== fused row-block fus-GEMM(448) + out/emb/prep epilogue ======================
// 32 rows/block, N=448, warps 0..6 do GEMM (64 cols each), K=512.
#define BPF 452
__global__ void k_fustep(const float* __restrict__ A /* h2_g */,
                         const float* __restrict__ W /* Wfusr 512x448 */,
                         const float* __restrict__ rfus /* rowfus_g */,
                         const float* __restrict__ Wout, const float* __restrict__ bout,
                         const float* __restrict__ Wemb, const float* __restrict__ bemb,
                         const float* __restrict__ loc, const float* __restrict__ feat,
                         const float* __restrict__ Wfus, const float* __restrict__ cffus,
                         float* __restrict__ dout, int f, int off)
{
    extern __shared__ float sm[];
    const int ASZ = 32 * 36, BSZ = 32 * BPF;
    float* Ast = sm;
    float* Bst = sm + 2 * ASZ;
    float* rb  = sm + 2 * ASZ + 2 * BSZ;   // 32 x BPF

    const int rows0 = blockIdx.x * 32;
    const int tid = threadIdx.x, w = tid >> 5, lane = tid & 31;
    const int l4 = lane >> 2, lm4 = lane & 3;
    const int ar = tid >> 3, akq = (tid & 7) * 4;

    float acc[2][8][4] = {};   // warp w<7 uses nj<8 over 64 cols

    auto load = [&](int k0, int s) {
        float* as = Ast + s * ASZ;
        float* bs = Bst + s * BPF * 32;
        {
            unsigned d = (unsigned)__cvta_generic_to_shared(as + ar * 36 + akq);
            const float* g = A + (size_t)(rows0 + ar) * 512 + k0 + akq;
            asm volatile("cp.async.cg.shared.global [%0],[%1],16;\n" :: "r"(d), "l"(g));
        }
#pragma unroll
        for (int j = 0; j < 14; j++) {
            int id = tid + j * 256;
            int brow = id / 112, bc4 = (id % 112) * 4;
            unsigned d = (unsigned)__cvta_generic_to_shared(bs + brow * BPF + bc4);
            const float* g = W + (size_t)(k0 + brow) * 448 + bc4;
            asm volatile("cp.async.cg.shared.global [%0],[%1],16;\n" :: "r"(d), "l"(g));
        }
        asm volatile("cp.async.commit_group;\n");
    };

    const int nslab = 512 >> 5;  // 16
    load(0, 0);
    load(32, 1);

    for (int k = 0; k < nslab; k++) {
        asm volatile("cp.async.wait_group 1;\n");
        __syncthreads();
        const float* as = Ast + (k & 1) * ASZ;
        const float* bs = Bst + (k & 1) * BPF * 32;
        if (w < 7) {
#pragma unroll
            for (int ks = 0; ks < 4; ks++) {
                const int kk = ks * 8;
                unsigned a[2][4], b[8][2];
#pragma unroll
                for (int mi = 0; mi < 2; mi++) {
                    int mb = mi * 16 + l4;
                    a[mi][0] = __float_as_uint(as[mb * 36 + kk + lm4]);
                    a[mi][1] = __float_as_uint(as[(mb + 8) * 36 + kk + lm4]);
                    a[mi][2] = __float_as_uint(as[mb * 36 + kk + lm4 + 4]);
                    a[mi][3] = __float_as_uint(as[(mb + 8) * 36 + kk + lm4 + 4]);
                }
#pragma unroll
                for (int nj = 0; nj < 8; nj++) {
                    int nb = w * 64 + nj * 8 + l4;
                    b[nj][0] = __float_as_uint(bs[(kk + lm4) * BPF + nb]);
                    b[nj][1] = __float_as_uint(bs[(kk + lm4 + 4) * BPF + nb]);
                }
#pragma unroll
                for (int mi = 0; mi < 2; mi++)
#pragma unroll
                    for (int nj = 0; nj < 8; nj++)
                        mma8(acc[mi][nj], a[mi], b[nj]);
            }
        }
        __syncthreads();
        if (k + 2 < nslab) load((k + 2) * 32, k & 1);
        else               asm volatile("cp.async.commit_group;\n");
    }

    if (w < 7) {
#pragma unroll
        for (int mi = 0; mi < 2; mi++)
#pragma unroll
            for (int nj = 0; nj < 8; nj++)
#pragma unroll
                for (int h = 0; h < 2; h++) {
                    int r = mi * 16 + l4 + h * 8;
                    int c = w * 64 + nj * 8 + lm4 * 2;
                    rb[r * BPF + c]     = acc[mi][nj][h * 2 + 0]
                                        + rfus[(size_t)(rows0 + r) * 448 + c];
                    rb[r * BPF + c + 1] = acc[mi][nj][h * 2 + 1]
                                        + rfus[(size_t)(rows0 + r) * 448 + c + 1];
                }
    }
    __syncthreads();

    // epilogue: warp w handles rows 4w .. 4w+3
    const int fn = f + 1;
#pragma unroll
    for (int rr = 0; rr < 4; rr++) {
        int row = w * 4 + rr;
        int bm = off + rows0 + row;
        int b = bm & 255, m = bm >> 8;
        float s0 = 0.f, s1 = 0.f;
#pragma unroll
        for (int j = 0; j < 14; j++) {
            int c = lane + j * 32;
            float v = rb[row * BPF + c];
            s0 += v * Wout[c * 2 + 0];
            s1 += v * Wout[c * 2 + 1];
        }
#pragma unroll
        for (int o = 16; o; o >>= 1) {
            s0 += __shfl_xor_sync(0xffffffffu, s0, o);
            s1 += __shfl_xor_sync(0xffffffffu, s1, o);
        }
        float o0 = s0 + bout[0];
        float o1 = s1 + bout[1];
        if (lane == 0) {
            int t = f - OBS;
            dout[b * (NM * HOR * 2) + m * (HOR * 2) + t * 2 + 0] = o0;
            dout[b * (NM * HOR * 2) + m * (HOR * 2) + t * 2 + 1] = o1;
        }
        float e = fmaxf(o0 * Wemb[lane] + o1 * Wemb[32 + lane] + bemb[lane], 0.f);
        if (fn < OBS + HOR) {
            float gx = loc[(b * NM + m) * 2 + 0], gy = loc[(b * NM + m) * 2 + 1];
            float dx = gx - o0, dy = gy - o1;
            float t = (float)fn;
            float exv;
            if (lane < 8)       exv = (lane & 1) ? gy : gx;
            else if (lane < 16) exv = (lane & 1) ? o1 : o0;
            else if (lane < 24) exv = (lane & 1) ? dy : dx;
            else                exv = t;
            g_E[bm * 64 + lane]      = tfr(exv);
            g_E[bm * 64 + 32 + lane] = tfr(e);
            // xlast: j=0 -> emb, j=1 -> extras, j>=2 -> feat
            g_xlast[(size_t)bm * 512 + lane]      = e;
            g_xlast[(size_t)bm * 512 + 32 + lane] = exv;
#pragma unroll
            for (int j = 2; j < 16; j++) {
                int c = lane + j * 32;
                g_xlast[(size_t)bm * 512 + c] = feat[b * INC + (c - 64)];
            }
#pragma unroll
            for (int j = 0; j < 14; j++) {
                int c = lane + j * 32;
                float v = cffus[b * 448 + c];
                v += o0 * Wfus[(512 + 0) * 448 + c];
                v += o1 * Wfus[(512 + 1) * 448 + c];
                v += gx * Wfus[(512 + 2) * 448 + c];
                v += gy * Wfus[(512 + 3) * 448 + c];
                v += dx * Wfus[(512 + 4) * 448 + c];
                v += dy * Wfus[(512 + 5) * 448 + c];
                v += t  * Wfus[(512 + 6) * 448 + c];
                g_rowfus[(size_t)bm * 448 + c] = v;
            }
        }
    }
}

// --------------- legacy converting GEMM core (setup paths only) -------------------
__device__ __forceinline__ void gemm0_body(const float* __restrict__ A, int lda,
                                           const float* __restrict__ Bm, int ldb,
                                           void* __restrict__ Cv, int ldc, int K,
                                           const float* __restrict__ bias, int obf16)
{
    __shared__ __align__(16) unsigned As[128 * 36];
    __shared__ __align__(16) unsigned Bs[32 * 68];
    const int row0 = blockIdx.y * 128, col0 = blockIdx.x * 64;
    const int tid = threadIdx.x;
    const int warp = tid >> 5, lane = tid & 31;
    const int wm = warp >> 1, wn = warp & 1;
    const int l4 = lane >> 2, lm4 = lane & 3;
    const int ar = tid >> 3, akq = (tid & 7) * 4;
    const int br = tid >> 4, bcq = (tid & 15) * 4;

    float acc[2][4][4] = {};
    float4 pa[4], pb[2];
#pragma unroll
    for (int it = 0; it < 4; it++)
        pa[it] = *(const float4*)(A + (size_t)(row0 + ar + it * 32) * lda + akq);
#pragma unroll
    for (int it = 0; it < 2; it++)
        pb[it] = *(const float4*)(Bm + (size_t)(br + it * 16) * ldb + col0 + bcq);

    for (int k0 = 0; k0 < K; k0 += 32) {
#pragma unroll
        for (int it = 0; it < 4; it++) {
            unsigned* p = &As[(ar + it * 32) * 36 + akq];
            p[0] = f2tf(pa[it].x); p[1] = f2tf(pa[it].y);
            p[2] = f2tf(pa[it].z); p[3] = f2tf(pa[it].w);
        }
#pragma unroll
        for (int it = 0; it < 2; it++) {
            unsigned* p = &Bs[(br + it * 16) * 68 + bcq];
            p[0] = f2tf(pb[it].x); p[1] = f2tf(pb[it].y);
            p[2] = f2tf(pb[it].z); p[3] = f2tf(pb[it].w);
        }
        __syncthreads();
        if (k0 + 32 < K) {
#pragma unroll
            for (int it = 0; it < 4; it++)
                pa[it] = *(const float4*)(A + (size_t)(row0 + ar + it * 32) * lda + k0 + 32 + akq);
#pragma unroll
            for (int it = 0; it < 2; it++)
                pb[it] = *(const float4*)(Bm + (size_t)(k0 + 32 + br + it * 16) * ldb + col0 + bcq);
        }
#pragma unroll
        for (int ks = 0; ks < 4; ks++) {
            const int kk = ks * 8;
            unsigned a[2][4], b[4][2];
#pragma unroll
            for (int mi = 0; mi < 2; mi++) {
                int mb = wm * 32 + mi * 16 + l4;
                a[mi][0] = As[mb * 36 + kk + lm4];
                a[mi][1] = As[(mb + 8) * 36 + kk + lm4];
                a[mi][2] = As[mb * 36 + kk + lm4 + 4];
                a[mi][3] = As[(mb + 8) * 36 + kk + lm4 + 4];
            }
#pragma unroll
            for (int nj = 0; nj < 4; nj++) {
                int nb = wn * 32 + nj * 8 + l4;
                b[nj][0] = Bs[(kk + lm4) * 68 + nb];
                b[nj][1] = Bs[(kk + lm4 + 4) * 68 + nb];
            }
#pragma unroll
            for (int mi = 0; mi < 2; mi++)
#pragma unroll
                for (int nj = 0; nj < 4; nj++)
                    mma8(acc[mi][nj], a[mi], b[nj]);
        }
        __syncthreads();
    }
#pragma unroll
    for (int mi = 0; mi < 2; mi++) {
        const int rb = row0 + wm * 32 + mi * 16 + l4;
#pragma unroll
        for (int nj = 0; nj < 4; nj++) {
            const int c = col0 + wn * 32 + nj * 8 + lm4 * 2;
#pragma unroll
            for (int h = 0; h < 2; h++) {
                const int r = rb + h * 8;
                float v0 = acc[mi][nj][h * 2 + 0];
                float v1 = acc[mi][nj][h * 2 + 1];
                if (bias) { v0 += bias[c]; v1 += bias[c + 1]; }
                if (obf16) {
                    *(__nv_bfloat162*)((__nv_bfloat16*)Cv + (size_t)r * ldc + c) =
                        __floats2bfloat162_rn(v0, v1);
                } else {
                    *(float2*)((float*)Cv + (size_t)r * ldc + c) = make_float2(v0, v1);
                }
            }
        }
    }
}

__global__ void k_gemms(const float* __restrict__ feat,
                        const float* __restrict__ Wqkv, const float* __restrict__ bqkv,
                        const float* __restrict__ Wfus, const float* __restrict__ bfus)
{
    if (blockIdx.z == 0) {
        if (blockIdx.x >= 24 || blockIdx.y >= 2) return;
        gemm0_body(feat, 448, Wqkv + 64 * 1536, 1536, g_cfeat, 1536, 448, bqkv, 0);
    } else if (blockIdx.z == 1) {
        if (blockIdx.x >= 7 || blockIdx.y >= 2) return;
        gemm0_body(feat, 448, Wfus + 519 * 448, 448, g_cffus, 448, 448, bfus, 0);
    } else {
        if (blockIdx.x >= 16 || blockIdx.y >= 40) return;
        gemm0_body(g_eobs, 32, Wqkv + 512, 1536, g_eKVo, 1024, 32, (const float*)0, 1);
    }
}

// ---------------- one-time: weights + Wcat + obs embeddings -----------------------
__global__ void k_setup(const float* __restrict__ Wqkv, const float* __restrict__ Wo,
                        const float* __restrict__ Wff1, const float* __restrict__ Wff2,
                        const float* __restrict__ Wfus,
                        const float* __restrict__ obs, const float* __restrict__ Wemb,
                        const float* __restrict__ bemb)
{
    int i = blockIdx.x * 256 + threadIdx.x;
    const int N0 = 64 * 2560, N1 = 512 * 512, N2 = 512 * 2048,
              N3 = 2048 * 512, N4 = 512 * 448, N5 = OBS * NB * 32;
    if (i < N0) {
        int r = i / 2560, c = i - r * 2560;
        float v;
        if (c < 1536)
            v = (r < 32) ? Wqkv[(32 + r) * 1536 + c]
                         : ((c < 512) ? Wqkv[(r - 32) * 1536 + c] : 0.f);
        else
            v = (r < 32) ? 0.f : Wqkv[(r - 32) * 1536 + 512 + (c - 1536)];
        g_Wcat[i] = tfr(v);
        return;
    }
    i -= N0;
    if (i < N1) { g_Wor[i]   = tfr(Wo[i]);   return; } i -= N1;
    if (i < N2) { g_Wff1r[i] = tfr(Wff1[i]); return; } i -= N2;
    if (i < N3) { g_Wff2r[i] = tfr(Wff2[i]); return; } i -= N3;
    if (i < N4) { g_Wfusr[i] = tfr(Wfus[i]); return; } i -= N4;
    if (i < N5) {
        int d = i >> 5, t = i & 31;
        int b = d / OBS, l = d - b * OBS;
        float o0 = obs[(l * NB + b) * 2 + 0];
        float o1 = obs[(l * NB + b) * 2 + 1];
        g_eobs[i] = fmaxf(o0 * Wemb[t] + o1 * Wemb[32 + t] + bemb[t], 0.f);
    }
}

__global__ void k_initprep(const float* __restrict__ obs, const float* __restrict__ Wemb,
                           const float* __restrict__ bemb,
                           const float* __restrict__ loc, const float* __restrict__ feat,
                           const float* __restrict__ Wfus)
{
    int bm = blockIdx.x, tid = threadIdx.x;
    int b = bm & 255, m = bm >> 8;
    float lx = obs[((OBS - 1) * NB + b) * 2 + 0];
    float ly = obs[((OBS - 1) * NB + b) * 2 + 1];
    __shared__ float se[32], ex[32];
    if (tid < 32)
        se[tid] = fmaxf(lx * Wemb[tid] + ly * Wemb[32 + tid] + bemb[tid], 0.f);
    float gx = loc[(b * NM + m) * 2 + 0], gy = loc[(b * NM + m) * 2 + 1];
    float dx = gx - lx, dy = gy - ly;
    float t = (float)OBS;
    __syncthreads();
    if (tid < 32) {
        float v;
        if (tid < 8)       v = (tid & 1) ? gy : gx;
        else if (tid < 16) v = (tid & 1) ? ly : lx;
        else if (tid < 24) v = (tid & 1) ? dy : dx;
        else               v = t;
        ex[tid] = v;
        g_E[bm * 64 + tid] = tfr(v);
        g_E[bm * 64 + 32 + tid] = tfr(se[tid]);
    }
    __syncthreads();
    for (int c = tid; c < 512; c += 128) {
        float v;
        if (c < 32)      v = se[c];
        else if (c < 64) v = ex[c - 32];
        else             v = feat[b * INC + (c - 64)];
        g_xlast[bm * 512 + c] = v;
    }
    for (int c = tid; c < 448; c += 128) {
        float v = g_cffus[b * 448 + c];
        v += lx * Wfus[(512 + 0) * 448 + c];
        v += ly * Wfus[(512 + 1) * 448 + c];
        v += gx * Wfus[(512 + 2) * 448 + c];
        v += gy * Wfus[(512 + 3) * 448 + c];
        v += dx * Wfus[(512 + 4) * 448 + c];
        v += dy * Wfus[(512 + 5) * 448 + c];
        v += t  * Wfus[(512 + 6) * 448 + c];
        g_rowfus[bm * 448 + c] = v;
    }
}

// ------------------------- per-step attention -------------------------------------
__global__ void k_attn(int f, int bm0)
{
    int bm = blockIdx.x + bm0;
    int tid = threadIdx.x, w = tid >> 5, lane = tid & 31;
    int b = bm & 255;
    const float* qp = g_QKVC + (size_t)bm * 1536 + w * 64;
    float q0 = qp[2 * lane], q1 = qp[2 * lane + 1];
    const float* ckp = qp + 512;
    float s = q0 * ckp[2 * lane] + q1 * ckp[2 * lane + 1];
#pragma unroll
    for (int o = 16; o; o >>= 1) s += __shfl_xor_sync(0xffffffffu, s, o);
    const float qdot = s;
    __shared__ float sp[8][56];
    const int off = w * 64 + 2 * lane;
    const __nv_bfloat16* ob = g_eKVo + (size_t)b * OBS * 1024 + off;
    const __nv_bfloat16* rbp = g_eKV + (size_t)bm * HOR * 1024 + off;
    const int fr = f - OBS;
    for (int l = 0; l < OBS; l++) {
        float2 kf = __bfloat1622float2(*(const __nv_bfloat162*)(ob + l * 1024));
        float d = q0 * kf.x + q1 * kf.y;
#pragma unroll
        for (int o = 16; o; o >>= 1) d += __shfl_xor_sync(0xffffffffu, d, o);
        if (lane == 0) sp[w][l] = (d + qdot) * 0.125f;
    }
    for (int l = 0; l < fr; l++) {
        float2 kf = __bfloat1622float2(*(const __nv_bfloat162*)(rbp + l * 1024));
        float d = q0 * kf.x + q1 * kf.y;
#pragma unroll
        for (int o = 16; o; o >>= 1) d += __shfl_xor_sync(0xffffffffu, d, o);
        if (lane == 0) sp[w][OBS + l] = (d + qdot) * 0.125f;
    }
    __syncwarp();
    float mx = -1e30f;
    if (lane < f)      mx = sp[w][lane];
    if (lane + 32 < f) mx = fmaxf(mx, sp[w][lane + 32]);
#pragma unroll
    for (int o = 16; o; o >>= 1) mx = fmaxf(mx, __shfl_xor_sync(0xffffffffu, mx, o));
    float e0 = 0.f, e1 = 0.f;
    if (lane < f)      e0 = expf(sp[w][lane] - mx);
    if (lane + 32 < f) e1 = expf(sp[w][lane + 32] - mx);
    float sum = e0 + e1;
#pragma unroll
    for (int o = 16; o; o >>= 1) sum += __shfl_xor_sync(0xffffffffu, sum, o);
    if (lane < f)      sp[w][lane] = e0;
    if (lane + 32 < f) sp[w][lane + 32] = e1;
    __syncwarp();
    float inv = 1.f / sum;
    const float* cvp = qp + 1024;
    float a0 = 0.f, a1 = 0.f;
    for (int l = 0; l < OBS; l++) {
        float p = sp[w][l];
        float2 vf = __bfloat1622float2(*(const __nv_bfloat162*)(ob + 512 + l * 1024));
        a0 += p * vf.x; a1 += p * vf.y;
    }
    for (int l = 0; l < fr; l++) {
        float p = sp[w][OBS + l];
        float2 vf = __bfloat1622float2(*(const __nv_bfloat162*)(rbp + 512 + l * 1024));
        a0 += p * vf.x; a1 += p * vf.y;
    }
    float* op = g_ctx + (size_t)bm * 512 + off;
    *(float2*)op = make_float2(tfr(cvp[2 * lane] + a0 * inv),
                               tfr(cvp[2 * lane + 1] + a1 * inv));
}

// ----------------------------------- launch ---------------------------------------
extern "C" void kernel_launch(void* const* d_in, const int* in_sizes, int n_in,
                              void* d_out, int out_size)
{
    const float* feat = (const float*)d_in[0];
    const float* loc  = (const float*)d_in[1];
    const float* obs  = (const float*)d_in[2];
    const float* Wemb = (const float*)d_in[3];
    const float* bemb = (const float*)d_in[4];
    const float* Wqkv = (const float*)d_in[5];
    const float* bqkv = (const float*)d_in[6];
    const float* Wo   = (const float*)d_in[7];
    const float* bo   = (const float*)d_in[8];
    const float* Wff1 = (const float*)d_in[9];
    const float* bff1 = (const float*)d_in[10];
    const float* Wff2 = (const float*)d_in[11];
    const float* bff2 = (const float*)d_in[12];
    const float* ln1g = (const float*)d_in[13];
    const float* ln1b = (const float*)d_in[14];
    const float* ln2g = (const float*)d_in[15];
    const float* ln2b = (const float*)d_in[16];
    const float* Wfus = (const float*)d_in[17];
    const float* bfus = (const float*)d_in[18];
    const float* Wout = (const float*)d_in[19];
    const float* bout = (const float*)d_in[20];
    float* outp = (float*)d_out;

    float *cfeat, *cffus, *E, *xlast, *rowfus, *QKVC, *ctx, *h1, *ff1, *h2,
          *Wor, *Wff1r, *Wff2r, *Wfusr, *Wcat;
    __nv_bfloat16 *eKV;
    cudaGetSymbolAddress((void**)&cfeat,  g_cfeat);
    cudaGetSymbolAddress((void**)&cffus,  g_cffus);
    cudaGetSymbolAddress((void**)&Wcat,   g_Wcat);
    cudaGetSymbolAddress((void**)&Wor,    g_Wor);
    cudaGetSymbolAddress((void**)&Wff1r,  g_Wff1r);
    cudaGetSymbolAddress((void**)&Wff2r,  g_Wff2r);
    cudaGetSymbolAddress((void**)&Wfusr,  g_Wfusr);
    cudaGetSymbolAddress((void**)&eKV,    g_eKV);
    cudaGetSymbolAddress((void**)&E,      g_E);
    cudaGetSymbolAddress((void**)&xlast,  g_xlast);
    cudaGetSymbolAddress((void**)&rowfus, g_rowfus);
    cudaGetSymbolAddress((void**)&QKVC,   g_QKVC);
    cudaGetSymbolAddress((void**)&ctx,    g_ctx);
    cudaGetSymbolAddress((void**)&h1,     g_h1);
    cudaGetSymbolAddress((void**)&ff1,    g_ff1);
    cudaGetSymbolAddress((void**)&h2,     g_h2);

    const float* NUL = (const float*)0;
    __nv_bfloat16* BNUL = (__nv_bfloat16*)0;

    const int SMEMT = 3 * (64 * 36 + 32 * 68) * 4;                   // 53760
    const int SMEMR = (2 * 32 * 36 + 2 * 32 * BPN + 32 * BPN) * 4;   // 207360
    const int SMEMF = (2 * 32 * 36 + 2 * 32 * BPF + 32 * BPF) * 4;   // 182784
    cudaFuncSetAttribute(k_gemmt,  cudaFuncAttributeMaxDynamicSharedMemorySize, SMEMT);
    cudaFuncSetAttribute(k_rowln,  cudaFuncAttributeMaxDynamicSharedMemorySize, SMEMR);
    cudaFuncSetAttribute(k_fustep, cudaFuncAttributeMaxDynamicSharedMemorySize, SMEMF);

    static cudaStream_t gs[NGRP - 1];
    static cudaEvent_t  evFork, evJoin[NGRP - 1];
    static int s_init = 0;
    if (!s_init) {
        for (int i = 0; i < NGRP - 1; i++)
            cudaStreamCreateWithFlags(&gs[i], cudaStreamNonBlocking);
        cudaEventCreateWithFlags(&evFork, cudaEventDisableTiming);
        for (int i = 0; i < NGRP - 1; i++)
            cudaEventCreateWithFlags(&evJoin[i], cudaEventDisableTiming);
        s_init = 1;
    }

    // ---- setup (main stream) ----
    const int NSET = 64 * 2560 + 512 * 512 + 512 * 2048 + 2048 * 512 + 512 * 448
                   + OBS * NB * 32;
    k_setup<<<(NSET + 255) / 256, 256>>>(Wqkv, Wo, Wff1, Wff2, Wfus, obs, Wemb, bemb);
    k_gemms<<<dim3(24, 40, 3), 256>>>(feat, Wqkv, bqkv, Wfus, bfus);
    k_initprep<<<BMT, 128>>>(obs, Wemb, bemb, loc, feat, Wfus);

    cudaEventRecord(evFork, 0);
    for (int i = 0; i < NGRP - 1; i++) cudaStreamWaitEvent(gs[i], evFork, 0);

    const int EKLD = HOR * 1024;
    const int GY = GROWS / 64;   // 8
    const int RB = GROWS / 32;   // 16 row-blocks per group
    for (int f = OBS; f < OBS + HOR; f++) {
        int ekoff = ((f == OBS) ? (HOR - 1) : (f - 1 - OBS)) * 1024;
        for (int g = 0; g < NGRP; g++) {
            cudaStream_t st = (g == 0) ? (cudaStream_t)0 : gs[g - 1];
            const int off = g * GROWS;
            float* Eg   = E + (size_t)off * 64;
            float* Qg   = QKVC + (size_t)off * 1536;
            float* ctxg = ctx + (size_t)off * 512;
            float* xlg  = xlast + (size_t)off * 512;
            float* h1g  = h1 + (size_t)off * 512;
            float* ff1g = ff1 + (size_t)off * 2048;
            float* h2g  = h2 + (size_t)off * 512;
            float* rfg  = rowfus + (size_t)off * 448;
            __nv_bfloat16* eKVg = eKV + (size_t)off * EKLD;

            // 1. QKVC + eKV (K=64)
            k_gemmt<<<dim3(40, GY), 256, SMEMT, st>>>(Eg, 64, Wcat, 2560, Qg, 1536, 64,
                                                      NUL, cfeat, 256, 1536, 0, 0,
                                                      eKVg, 1536, ekoff, EKLD);
            // 2. attention
            k_attn<<<GROWS, 256, 0, st>>>(f, off);
            // 3. h1 = LN1(xlast + ctx@Wo + bo)
            k_rowln<<<RB, 256, SMEMR, st>>>(ctxg, 512, 512, Wor, bo, xlg,
                                            ln1g, ln1b, h1g);
            // 4. ff1 = tf32(relu(h1 @ Wff1 + b))
            k_gemmt<<<dim3(32, GY), 256, SMEMT, st>>>(h1g, 512, Wff1r, 2048, ff1g, 2048,
                                                      512, bff1, NUL, 1, 0, 1, 1,
                                                      BNUL, 1 << 30, 0, 0);
            // 5. h2 = LN2(h1 + ff1@Wff2 + b)
            k_rowln<<<RB, 256, SMEMR, st>>>(ff1g, 2048, 2048, Wff2r, bff2, h1g,
                                            ln2g, ln2b, h2g);
            // 6. fus + out + emb + prep(f+1)
            k_fustep<<<RB, 256, SMEMF, st>>>(h2g, Wfusr, rfg, Wout, bout, Wemb, bemb,
                                             loc, feat, Wfus, cffus, outp, f, off);
        }
    }

    for (int i = 0; i < NGRP - 1; i++) {
        cudaEventRecord(evJoin[i], gs[i]);
        cudaStreamWaitEvent((cudaStream_t)0, evJoin[i], 0);
    }
    (void)in_sizes; (void)n_in; (void)out_size;
}

// round 14
// speedup vs baseline: 1.0561x; 1.0561x over previous
#include <cuda_runtime.h>
#include <cuda_bf16.h>
#include <math.h>

#define NB    256
#define NM    6
#define INC   448
#define EMB   32
#define OBS   20
#define HOR   30
#define DD    512
#define DFF   2048
#define BMT   1536     // NB*NM
#define NGRP  3        // 2 created streams + default: passes the memory guard
#define GROWS (BMT / NGRP)   // 512 rows per group

// ------------------------- scratch (static device globals) -------------------------
__device__ __align__(256) float g_cfeat[NB*1536];
__device__ __align__(256) float g_cffus[NB*448];
__device__ __align__(256) float g_Wcat[64*2560];       // tf32; cols 1536:2560 = emb->eKV map
__device__ __align__(256) float g_Wor[512*512];
__device__ __align__(256) float g_Wff1r[512*2048];
__device__ __align__(256) float g_Wff2r[2048*512];
__device__ __align__(256) float g_Wfusr[512*448];
__device__ __align__(256) float g_eobs[OBS*NB*32];     // rows ordered [b][l]
__device__ __align__(256) __nv_bfloat16 g_eKVo[(size_t)NB*OBS*1024];   // [b][l][1024]
__device__ __align__(256) __nv_bfloat16 g_eKV[(size_t)BMT*HOR*1024];   // [bm][slot][1024]
__device__ __align__(256) float g_E[BMT*64];
__device__ __align__(256) float g_xlast[BMT*DD];
__device__ __align__(256) float g_rowfus[BMT*448];
__device__ __align__(256) float g_QKVC[BMT*1536];
__device__ __align__(256) float g_ctx[BMT*DD];
__device__ __align__(256) float g_wo[BMT*DD];
__device__ __align__(256) float g_wob[BMT*DD];
__device__ __align__(256) float g_h1[BMT*DD];
__device__ __align__(256) float g_ff1[BMT*DFF];
__device__ __align__(256) float g_ff2[BMT*DD];
__device__ __align__(256) float g_ff2b[BMT*DD];
__device__ __align__(256) float g_h2[BMT*DD];
__device__ __align__(256) float g_fus[BMT*448];
__device__ __align__(256) float g_fusb[BMT*448];

// --------------------------- TF32 helpers ----------------------------------------
__device__ __forceinline__ unsigned f2tf(float x) {
    unsigned u;
    asm("cvt.rna.tf32.f32 %0, %1;" : "=r"(u) : "f"(x));
    return u;
}
__device__ __forceinline__ float tfr(float x) { return __uint_as_float(f2tf(x)); }

__device__ __forceinline__ void mma8(float* d, const unsigned* a, const unsigned* b) {
    asm volatile(
        "mma.sync.aligned.m16n8k8.row.col.f32.tf32.tf32.f32 "
        "{%0,%1,%2,%3}, {%4,%5,%6,%7}, {%8,%9}, {%0,%1,%2,%3};"
        : "+f"(d[0]), "+f"(d[1]), "+f"(d[2]), "+f"(d[3])
        : "r"(a[0]), "r"(a[1]), "r"(a[2]), "r"(a[3]), "r"(b[0]), "r"(b[1]));
}

// ============ TF32 GEMM: 64x64 tile, 3-stage cp.async (tf32-pre-rounded) ==========
// gridDim.z==2 -> split-K: z=1 does upper K half into C2 (no bias/rowadd).
// EK != null: blocks with col0 >= ekcol write bf16 to EK[r*ekld + ekoff + (c-ekcol)].
__global__ void k_gemmt(const float* __restrict__ A, int lda,
                        const float* __restrict__ Bm, int ldb,
                        float* __restrict__ C, int ldc, int K,
                        const float* __restrict__ bias,
                        const float* __restrict__ rowadd, int ramod, int ldra,
                        int relu, int otf32, float* __restrict__ C2,
                        __nv_bfloat16* __restrict__ EK, int ekcol, int ekoff, int ekld)
{
    const int BPAD = 68, ASZ = 64 * 36, BSZ = 32 * BPAD;
    extern __shared__ float sm[];
    float* AsB = sm;            // 3 stages
    float* BsB = sm + 3 * ASZ;

    if (blockIdx.z) { A += K; Bm += (size_t)K * ldb; C = C2; bias = 0; rowadd = 0; }

    const int row0 = blockIdx.y * 64, col0 = blockIdx.x * 64;
    const int tid = threadIdx.x, warp = tid >> 5, lane = tid & 31;
    const int wm = warp >> 2, wn = warp & 3;
    const int l4 = lane >> 2, lm4 = lane & 3;
    const int ar = tid >> 3, akq = (tid & 7) * 4;
    const int brow0 = tid >> 4, bc4 = (tid & 15) * 4;

    float acc[2][2][4] = {};

    auto load = [&](int k0, int s) {
        float* as = AsB + s * ASZ;
        float* bs = BsB + s * BSZ;
#pragma unroll
        for (int i = 0; i < 2; i++) {
            unsigned d = (unsigned)__cvta_generic_to_shared(as + (ar + i * 32) * 36 + akq);
            const float* g = A + (size_t)(row0 + ar + i * 32) * lda + k0 + akq;
            asm volatile("cp.async.cg.shared.global [%0],[%1],16;\n" :: "r"(d), "l"(g));
        }
#pragma unroll
        for (int i = 0; i < 2; i++) {
            int row = brow0 + i * 16;
            unsigned d = (unsigned)__cvta_generic_to_shared(bs + row * BPAD + bc4);
            const float* g = Bm + (size_t)(k0 + row) * ldb + col0 + bc4;
            asm volatile("cp.async.cg.shared.global [%0],[%1],16;\n" :: "r"(d), "l"(g));
        }
        asm volatile("cp.async.commit_group;\n");
    };

    const int nslab = K >> 5;
    load(0, 0);
    if (nslab > 1) load(32, 1); else asm volatile("cp.async.commit_group;\n");

    for (int k = 0; k < nslab; k++) {
        asm volatile("cp.async.wait_group 1;\n");
        __syncthreads();
        if (k + 2 < nslab) load((k + 2) * 32, (k + 2) % 3);
        else               asm volatile("cp.async.commit_group;\n");
        const float* as = AsB + (k % 3) * ASZ;
        const float* bs = BsB + (k % 3) * BSZ;
#pragma unroll
        for (int ks = 0; ks < 4; ks++) {
            const int kk = ks * 8;
            unsigned a[2][4], b[2][2];
#pragma unroll
            for (int mi = 0; mi < 2; mi++) {
                int mb = wm * 32 + mi * 16 + l4;
                a[mi][0] = __float_as_uint(as[mb * 36 + kk + lm4]);
                a[mi][1] = __float_as_uint(as[(mb + 8) * 36 + kk + lm4]);
                a[mi][2] = __float_as_uint(as[mb * 36 + kk + lm4 + 4]);
                a[mi][3] = __float_as_uint(as[(mb + 8) * 36 + kk + lm4 + 4]);
            }
#pragma unroll
            for (int nj = 0; nj < 2; nj++) {
                int nb = wn * 16 + nj * 8 + l4;
                b[nj][0] = __float_as_uint(bs[(kk + lm4) * BPAD + nb]);
                b[nj][1] = __float_as_uint(bs[(kk + lm4 + 4) * BPAD + nb]);
            }
#pragma unroll
            for (int mi = 0; mi < 2; mi++)
#pragma unroll
                for (int nj = 0; nj < 2; nj++)
                    mma8(acc[mi][nj], a[mi], b[nj]);
        }
        __syncthreads();
    }

    const bool ekreg = (EK != 0) && (col0 >= ekcol);
#pragma unroll
    for (int mi = 0; mi < 2; mi++) {
        const int rb = row0 + wm * 32 + mi * 16 + l4;
#pragma unroll
        for (int nj = 0; nj < 2; nj++) {
            const int c = col0 + wn * 16 + nj * 8 + lm4 * 2;
#pragma unroll
            for (int h = 0; h < 2; h++) {
                const int r = rb + h * 8;
                float v0 = acc[mi][nj][h * 2 + 0];
                float v1 = acc[mi][nj][h * 2 + 1];
                if (ekreg) {
                    *(__nv_bfloat162*)(EK + (size_t)r * ekld + ekoff + (c - ekcol)) =
                        __floats2bfloat162_rn(v0, v1);
                    continue;
                }
                if (bias) { v0 += bias[c]; v1 += bias[c + 1]; }
                if (rowadd) {
                    const float* ra = rowadd + (size_t)(r % ramod) * ldra + c;
                    v0 += ra[0]; v1 += ra[1];
                }
                if (relu) { v0 = fmaxf(v0, 0.f); v1 = fmaxf(v1, 0.f); }
                if (otf32) { v0 = tfr(v0); v1 = tfr(v1); }
                *(float2*)(C + (size_t)r * ldc + c) = make_float2(v0, v1);
            }
        }
    }
}

// --------------- legacy converting GEMM core (setup paths only) -------------------
__device__ __forceinline__ void gemm0_body(const float* __restrict__ A, int lda,
                                           const float* __restrict__ Bm, int ldb,
                                           void* __restrict__ Cv, int ldc, int K,
                                           const float* __restrict__ bias, int obf16)
{
    __shared__ __align__(16) unsigned As[128 * 36];
    __shared__ __align__(16) unsigned Bs[32 * 68];
    const int row0 = blockIdx.y * 128, col0 = blockIdx.x * 64;
    const int tid = threadIdx.x;
    const int warp = tid >> 5, lane = tid & 31;
    const int wm = warp >> 1, wn = warp & 1;
    const int l4 = lane >> 2, lm4 = lane & 3;
    const int ar = tid >> 3, akq = (tid & 7) * 4;
    const int br = tid >> 4, bcq = (tid & 15) * 4;

    float acc[2][4][4] = {};
    float4 pa[4], pb[2];
#pragma unroll
    for (int it = 0; it < 4; it++)
        pa[it] = *(const float4*)(A + (size_t)(row0 + ar + it * 32) * lda + akq);
#pragma unroll
    for (int it = 0; it < 2; it++)
        pb[it] = *(const float4*)(Bm + (size_t)(br + it * 16) * ldb + col0 + bcq);

    for (int k0 = 0; k0 < K; k0 += 32) {
#pragma unroll
        for (int it = 0; it < 4; it++) {
            unsigned* p = &As[(ar + it * 32) * 36 + akq];
            p[0] = f2tf(pa[it].x); p[1] = f2tf(pa[it].y);
            p[2] = f2tf(pa[it].z); p[3] = f2tf(pa[it].w);
        }
#pragma unroll
        for (int it = 0; it < 2; it++) {
            unsigned* p = &Bs[(br + it * 16) * 68 + bcq];
            p[0] = f2tf(pb[it].x); p[1] = f2tf(pb[it].y);
            p[2] = f2tf(pb[it].z); p[3] = f2tf(pb[it].w);
        }
        __syncthreads();
        if (k0 + 32 < K) {
#pragma unroll
            for (int it = 0; it < 4; it++)
                pa[it] = *(const float4*)(A + (size_t)(row0 + ar + it * 32) * lda + k0 + 32 + akq);
#pragma unroll
            for (int it = 0; it < 2; it++)
                pb[it] = *(const float4*)(Bm + (size_t)(k0 + 32 + br + it * 16) * ldb + col0 + bcq);
        }
#pragma unroll
        for (int ks = 0; ks < 4; ks++) {
            const int kk = ks * 8;
            unsigned a[2][4], b[4][2];
#pragma unroll
            for (int mi = 0; mi < 2; mi++) {
                int mb = wm * 32 + mi * 16 + l4;
                a[mi][0] = As[mb * 36 + kk + lm4];
                a[mi][1] = As[(mb + 8) * 36 + kk + lm4];
                a[mi][2] = As[mb * 36 + kk + lm4 + 4];
                a[mi][3] = As[(mb + 8) * 36 + kk + lm4 + 4];
            }
#pragma unroll
            for (int nj = 0; nj < 4; nj++) {
                int nb = wn * 32 + nj * 8 + l4;
                b[nj][0] = Bs[(kk + lm4) * 68 + nb];
                b[nj][1] = Bs[(kk + lm4 + 4) * 68 + nb];
            }
#pragma unroll
            for (int mi = 0; mi < 2; mi++)
#pragma unroll
                for (int nj = 0; nj < 4; nj++)
                    mma8(acc[mi][nj], a[mi], b[nj]);
        }
        __syncthreads();
    }
#pragma unroll
    for (int mi = 0; mi < 2; mi++) {
        const int rb = row0 + wm * 32 + mi * 16 + l4;
#pragma unroll
        for (int nj = 0; nj < 4; nj++) {
            const int c = col0 + wn * 32 + nj * 8 + lm4 * 2;
#pragma unroll
            for (int h = 0; h < 2; h++) {
                const int r = rb + h * 8;
                float v0 = acc[mi][nj][h * 2 + 0];
                float v1 = acc[mi][nj][h * 2 + 1];
                if (bias) { v0 += bias[c]; v1 += bias[c + 1]; }
                if (obf16) {
                    *(__nv_bfloat162*)((__nv_bfloat16*)Cv + (size_t)r * ldc + c) =
                        __floats2bfloat162_rn(v0, v1);
                } else {
                    *(float2*)((float*)Cv + (size_t)r * ldc + c) = make_float2(v0, v1);
                }
            }
        }
    }
}

// setup GEMMs, z-dispatch: z=0 cfeat, z=1 cffus, z=2 eKVo
__global__ void k_gemms(const float* __restrict__ feat,
                        const float* __restrict__ Wqkv, const float* __restrict__ bqkv,
                        const float* __restrict__ Wfus, const float* __restrict__ bfus)
{
    if (blockIdx.z == 0) {
        if (blockIdx.x >= 24 || blockIdx.y >= 2) return;
        gemm0_body(feat, 448, Wqkv + 64 * 1536, 1536, g_cfeat, 1536, 448, bqkv, 0);
    } else if (blockIdx.z == 1) {
        if (blockIdx.x >= 7 || blockIdx.y >= 2) return;
        gemm0_body(feat, 448, Wfus + 519 * 448, 448, g_cffus, 448, 448, bfus, 0);
    } else {
        if (blockIdx.x >= 16 || blockIdx.y >= 40) return;
        gemm0_body(g_eobs, 32, Wqkv + 512, 1536, g_eKVo, 1024, 32, (const float*)0, 1);
    }
}

// ---------------- one-time: weights + Wcat + obs embeddings -----------------------
__global__ void k_setup(const float* __restrict__ Wqkv, const float* __restrict__ Wo,
                        const float* __restrict__ Wff1, const float* __restrict__ Wff2,
                        const float* __restrict__ Wfus,
                        const float* __restrict__ obs, const float* __restrict__ Wemb,
                        const float* __restrict__ bemb)
{
    int i = blockIdx.x * 256 + threadIdx.x;
    const int N0 = 64 * 2560, N1 = 512 * 512, N2 = 512 * 2048,
              N3 = 2048 * 512, N4 = 512 * 448, N5 = OBS * NB * 32;
    if (i < N0) {
        int r = i / 2560, c = i - r * 2560;
        float v;
        if (c < 1536)
            v = (r < 32) ? Wqkv[(32 + r) * 1536 + c]
                         : ((c < 512) ? Wqkv[(r - 32) * 1536 + c] : 0.f);
        else
            v = (r < 32) ? 0.f : Wqkv[(r - 32) * 1536 + 512 + (c - 1536)];
        g_Wcat[i] = tfr(v);
        return;
    }
    i -= N0;
    if (i < N1) { g_Wor[i]   = tfr(Wo[i]);   return; } i -= N1;
    if (i < N2) { g_Wff1r[i] = tfr(Wff1[i]); return; } i -= N2;
    if (i < N3) { g_Wff2r[i] = tfr(Wff2[i]); return; } i -= N3;
    if (i < N4) { g_Wfusr[i] = tfr(Wfus[i]); return; } i -= N4;
    if (i < N5) {
        int d = i >> 5, t = i & 31;
        int b = d / OBS, l = d - b * OBS;
        float o0 = obs[(l * NB + b) * 2 + 0];
        float o1 = obs[(l * NB + b) * 2 + 1];
        g_eobs[i] = fmaxf(o0 * Wemb[t] + o1 * Wemb[32 + t] + bemb[t], 0.f);
    }
}

__global__ void k_initprep(const float* __restrict__ obs, const float* __restrict__ Wemb,
                           const float* __restrict__ bemb,
                           const float* __restrict__ loc, const float* __restrict__ feat,
                           const float* __restrict__ Wfus)
{
    int bm = blockIdx.x, tid = threadIdx.x;
    int b = bm & 255, m = bm >> 8;
    float lx = obs[((OBS - 1) * NB + b) * 2 + 0];
    float ly = obs[((OBS - 1) * NB + b) * 2 + 1];
    __shared__ float se[32], ex[32];
    if (tid < 32)
        se[tid] = fmaxf(lx * Wemb[tid] + ly * Wemb[32 + tid] + bemb[tid], 0.f);
    float gx = loc[(b * NM + m) * 2 + 0], gy = loc[(b * NM + m) * 2 + 1];
    float dx = gx - lx, dy = gy - ly;
    float t = (float)OBS;
    __syncthreads();
    if (tid < 32) {
        float v;
        if (tid < 8)       v = (tid & 1) ? gy : gx;
        else if (tid < 16) v = (tid & 1) ? ly : lx;
        else if (tid < 24) v = (tid & 1) ? dy : dx;
        else               v = t;
        ex[tid] = v;
        g_E[bm * 64 + tid] = tfr(v);
        g_E[bm * 64 + 32 + tid] = tfr(se[tid]);
    }
    __syncthreads();
    for (int c = tid; c < 512; c += 128) {
        float v;
        if (c < 32)      v = se[c];
        else if (c < 64) v = ex[c - 32];
        else             v = feat[b * INC + (c - 64)];
        g_xlast[bm * 512 + c] = v;
    }
    for (int c = tid; c < 448; c += 128) {
        float v = g_cffus[b * 448 + c];
        v += lx * Wfus[(512 + 0) * 448 + c];
        v += ly * Wfus[(512 + 1) * 448 + c];
        v += gx * Wfus[(512 + 2) * 448 + c];
        v += gy * Wfus[(512 + 3) * 448 + c];
        v += dx * Wfus[(512 + 4) * 448 + c];
        v += dy * Wfus[(512 + 5) * 448 + c];
        v += t  * Wfus[(512 + 6) * 448 + c];
        g_rowfus[bm * 448 + c] = v;
    }
}

// ------------------------- per-step attention (bm0 = group row base) ---------------
__global__ void k_attn(int f, int bm0)
{
    int bm = blockIdx.x + bm0;
    int tid = threadIdx.x, w = tid >> 5, lane = tid & 31;
    int b = bm & 255;
    const float* qp = g_QKVC + (size_t)bm * 1536 + w * 64;
    float q0 = qp[2 * lane], q1 = qp[2 * lane + 1];
    const float* ckp = qp + 512;
    float s = q0 * ckp[2 * lane] + q1 * ckp[2 * lane + 1];
#pragma unroll
    for (int o = 16; o; o >>= 1) s += __shfl_xor_sync(0xffffffffu, s, o);
    const float qdot = s;
    __shared__ float sp[8][56];
    const int off = w * 64 + 2 * lane;
    const __nv_bfloat16* ob = g_eKVo + (size_t)b * OBS * 1024 + off;
    const __nv_bfloat16* rbp = g_eKV + (size_t)bm * HOR * 1024 + off;
    const int fr = f - OBS;
    for (int l = 0; l < OBS; l++) {
        float2 kf = __bfloat1622float2(*(const __nv_bfloat162*)(ob + l * 1024));
        float d = q0 * kf.x + q1 * kf.y;
#pragma unroll
        for (int o = 16; o; o >>= 1) d += __shfl_xor_sync(0xffffffffu, d, o);
        if (lane == 0) sp[w][l] = (d + qdot) * 0.125f;
    }
    for (int l = 0; l < fr; l++) {
        float2 kf = __bfloat1622float2(*(const __nv_bfloat162*)(rbp + l * 1024));
        float d = q0 * kf.x + q1 * kf.y;
#pragma unroll
        for (int o = 16; o; o >>= 1) d += __shfl_xor_sync(0xffffffffu, d, o);
        if (lane == 0) sp[w][OBS + l] = (d + qdot) * 0.125f;
    }
    __syncwarp();
    float mx = -1e30f;
    if (lane < f)      mx = sp[w][lane];
    if (lane + 32 < f) mx = fmaxf(mx, sp[w][lane + 32]);
#pragma unroll
    for (int o = 16; o; o >>= 1) mx = fmaxf(mx, __shfl_xor_sync(0xffffffffu, mx, o));
    float e0 = 0.f, e1 = 0.f;
    if (lane < f)      e0 = expf(sp[w][lane] - mx);
    if (lane + 32 < f) e1 = expf(sp[w][lane + 32] - mx);
    float sum = e0 + e1;
#pragma unroll
    for (int o = 16; o; o >>= 1) sum += __shfl_xor_sync(0xffffffffu, sum, o);
    if (lane < f)      sp[w][lane] = e0;
    if (lane + 32 < f) sp[w][lane + 32] = e1;
    __syncwarp();
    float inv = 1.f / sum;
    const float* cvp = qp + 1024;
    float a0 = 0.f, a1 = 0.f;
    for (int l = 0; l < OBS; l++) {
        float p = sp[w][l];
        float2 vf = __bfloat1622float2(*(const __nv_bfloat162*)(ob + 512 + l * 1024));
        a0 += p * vf.x; a1 += p * vf.y;
    }
    for (int l = 0; l < fr; l++) {
        float p = sp[w][OBS + l];
        float2 vf = __bfloat1622float2(*(const __nv_bfloat162*)(rbp + 512 + l * 1024));
        a0 += p * vf.x; a1 += p * vf.y;
    }
    float* op = g_ctx + (size_t)bm * 512 + off;
    *(float2*)op = make_float2(tfr(cvp[2 * lane] + a0 * inv),
                               tfr(cvp[2 * lane + 1] + a1 * inv));
}

// --------------- layernorm: warp per row, out = tf32(LN(x1+x2+x3)*g+b) ------------
__global__ void k_ln(const float* __restrict__ x1, const float* __restrict__ x2,
                     const float* __restrict__ x3,
                     const float* __restrict__ g, const float* __restrict__ bb,
                     float* __restrict__ out)
{
    int w = threadIdx.x >> 5, lane = threadIdx.x & 31;
    int row = blockIdx.x * 8 + w;
    size_t base = (size_t)row * 512;
    float v[16];
    float sum = 0.f;
#pragma unroll
    for (int j = 0; j < 16; j++) {
        int e = lane + j * 32;
        v[j] = x1[base + e] + x2[base + e] + x3[base + e];
        sum += v[j];
    }
#pragma unroll
    for (int o = 16; o; o >>= 1) sum += __shfl_xor_sync(0xffffffffu, sum, o);
    float mu = sum * (1.f / 512.f);
    float var = 0.f;
#pragma unroll
    for (int j = 0; j < 16; j++) { float d = v[j] - mu; var += d * d; }
#pragma unroll
    for (int o = 16; o; o >>= 1) var += __shfl_xor_sync(0xffffffffu, var, o);
    float rs = rsqrtf(var * (1.f / 512.f) + 1e-5f);
#pragma unroll
    for (int j = 0; j < 16; j++) {
        int e = lane + j * 32;
        out[base + e] = tfr((v[j] - mu) * rs * g[e] + bb[e]);
    }
}

// ==== fused per-step epilogue + NEXT-step QKVC/eKV ================================
// Block = 16 bm's (warp w handles bm indices w and w+8). Phase 1: out/emb/xlast/
// rowfus per bm, stage E rows in smem. Phase 2: QKVC(f+1) = E @ Wcat (K=64, fp32
// FMA on tf32-rounded operands == exact TF32-MMA products) + eKV[f] bf16 emit.
__global__ void k_stepq(const float* __restrict__ Wout, const float* __restrict__ bout,
                        const float* __restrict__ Wemb, const float* __restrict__ bemb,
                        const float* __restrict__ loc, const float* __restrict__ feat,
                        const float* __restrict__ Wfus,
                        float* __restrict__ dout, int f, int off)
{
    __shared__ float E_sm[16][64];
    const int tid = threadIdx.x, w = tid >> 5, lane = tid & 31;
    const int bm0 = off + blockIdx.x * 16;
    const int fn = f + 1;
    const bool prep = (fn < OBS + HOR);

#pragma unroll
    for (int half = 0; half < 2; half++) {
        const int i = w + half * 8;
        const int bm = bm0 + i;
        const int b = bm & 255, m = bm >> 8;

        float s0 = 0.f, s1 = 0.f;
        const float* fp  = g_fus  + (size_t)bm * 448;
        const float* fpb = g_fusb + (size_t)bm * 448;
#pragma unroll
        for (int j = 0; j < 14; j++) {
            int c = lane + j * 32;
            float v = fp[c] + fpb[c];
            s0 += v * Wout[c * 2 + 0];
            s1 += v * Wout[c * 2 + 1];
        }
#pragma unroll
        for (int o = 16; o; o >>= 1) {
            s0 += __shfl_xor_sync(0xffffffffu, s0, o);
            s1 += __shfl_xor_sync(0xffffffffu, s1, o);
        }
        float o0 = s0 + bout[0];
        float o1 = s1 + bout[1];
        if (lane == 0) {
            int t = f - OBS;
            dout[b * (NM * HOR * 2) + m * (HOR * 2) + t * 2 + 0] = o0;
            dout[b * (NM * HOR * 2) + m * (HOR * 2) + t * 2 + 1] = o1;
        }
        if (prep) {
            float e = fmaxf(o0 * Wemb[lane] + o1 * Wemb[32 + lane] + bemb[lane], 0.f);
            float gx = loc[(b * NM + m) * 2 + 0], gy = loc[(b * NM + m) * 2 + 1];
            float dx = gx - o0, dy = gy - o1;
            float t = (float)fn;
            float exv;
            if (lane < 8)       exv = (lane & 1) ? gy : gx;
            else if (lane < 16) exv = (lane & 1) ? o1 : o0;
            else if (lane < 24) exv = (lane & 1) ? dy : dx;
            else                exv = t;
            E_sm[i][lane]      = tfr(exv);
            E_sm[i][32 + lane] = tfr(e);
            // xlast = [emb | extras | feat]
            g_xlast[(size_t)bm * 512 + lane]      = e;
            g_xlast[(size_t)bm * 512 + 32 + lane] = exv;
#pragma unroll
            for (int j = 2; j < 16; j++) {
                int c = lane + j * 32;
                g_xlast[(size_t)bm * 512 + c] = feat[b * INC + (c - 64)];
            }
#pragma unroll
            for (int j = 0; j < 14; j++) {
                int c = lane + j * 32;
                float v = g_cffus[b * 448 + c];
                v += o0 * Wfus[(512 + 0) * 448 + c];
                v += o1 * Wfus[(512 + 1) * 448 + c];
                v += gx * Wfus[(512 + 2) * 448 + c];
                v += gy * Wfus[(512 + 3) * 448 + c];
                v += dx * Wfus[(512 + 4) * 448 + c];
                v += dy * Wfus[(512 + 5) * 448 + c];
                v += t  * Wfus[(512 + 6) * 448 + c];
                g_rowfus[(size_t)bm * 448 + c] = v;
            }
        }
    }

    if (!prep) return;
    __syncthreads();

    // Phase 2: QKVC(f+1) + eKV[f] for the 16 bm's
    const int slot = f - OBS;
    for (int c = tid; c < 2560; c += 256) {
        float acc[16];
#pragma unroll
        for (int i = 0; i < 16; i++) acc[i] = 0.f;
        const float* wp = g_Wcat + c;
#pragma unroll 8
        for (int k = 0; k < 64; k++) {
            float wv = wp[k * 2560];
#pragma unroll
            for (int i = 0; i < 16; i++) acc[i] += E_sm[i][k] * wv;
        }
        if (c < 1536) {
#pragma unroll
            for (int i = 0; i < 16; i++) {
                int bm = bm0 + i;
                g_QKVC[(size_t)bm * 1536 + c] = acc[i] + g_cfeat[(bm & 255) * 1536 + c];
            }
        } else {
#pragma unroll
            for (int i = 0; i < 16; i++) {
                int bm = bm0 + i;
                g_eKV[(size_t)bm * (HOR * 1024) + slot * 1024 + (c - 1536)] =
                    __float2bfloat16(acc[i]);
            }
        }
    }
}

// ----------------------------------- launch ---------------------------------------
extern "C" void kernel_launch(void* const* d_in, const int* in_sizes, int n_in,
                              void* d_out, int out_size)
{
    const float* feat = (const float*)d_in[0];
    const float* loc  = (const float*)d_in[1];
    const float* obs  = (const float*)d_in[2];
    const float* Wemb = (const float*)d_in[3];
    const float* bemb = (const float*)d_in[4];
    const float* Wqkv = (const float*)d_in[5];
    const float* bqkv = (const float*)d_in[6];
    const float* Wo   = (const float*)d_in[7];
    const float* bo   = (const float*)d_in[8];
    const float* Wff1 = (const float*)d_in[9];
    const float* bff1 = (const float*)d_in[10];
    const float* Wff2 = (const float*)d_in[11];
    const float* bff2 = (const float*)d_in[12];
    const float* ln1g = (const float*)d_in[13];
    const float* ln1b = (const float*)d_in[14];
    const float* ln2g = (const float*)d_in[15];
    const float* ln2b = (const float*)d_in[16];
    const float* Wfus = (const float*)d_in[17];
    const float* bfus = (const float*)d_in[18];
    const float* Wout = (const float*)d_in[19];
    const float* bout = (const float*)d_in[20];
    float* outp = (float*)d_out;

    float *cfeat, *E, *xlast, *rowfus, *QKVC, *ctx, *wo, *wob, *h1, *ff1, *ff2,
          *ff2b, *h2, *fus, *fusb, *Wor, *Wff1r, *Wff2r, *Wfusr, *Wcat;
    __nv_bfloat16 *eKV;
    cudaGetSymbolAddress((void**)&cfeat,  g_cfeat);
    cudaGetSymbolAddress((void**)&Wcat,   g_Wcat);
    cudaGetSymbolAddress((void**)&Wor,    g_Wor);
    cudaGetSymbolAddress((void**)&Wff1r,  g_Wff1r);
    cudaGetSymbolAddress((void**)&Wff2r,  g_Wff2r);
    cudaGetSymbolAddress((void**)&Wfusr,  g_Wfusr);
    cudaGetSymbolAddress((void**)&eKV,    g_eKV);
    cudaGetSymbolAddress((void**)&E,      g_E);
    cudaGetSymbolAddress((void**)&xlast,  g_xlast);
    cudaGetSymbolAddress((void**)&rowfus, g_rowfus);
    cudaGetSymbolAddress((void**)&QKVC,   g_QKVC);
    cudaGetSymbolAddress((void**)&ctx,    g_ctx);
    cudaGetSymbolAddress((void**)&wo,     g_wo);
    cudaGetSymbolAddress((void**)&wob,    g_wob);
    cudaGetSymbolAddress((void**)&h1,     g_h1);
    cudaGetSymbolAddress((void**)&ff1,    g_ff1);
    cudaGetSymbolAddress((void**)&ff2,    g_ff2);
    cudaGetSymbolAddress((void**)&ff2b,   g_ff2b);
    cudaGetSymbolAddress((void**)&h2,     g_h2);
    cudaGetSymbolAddress((void**)&fus,    g_fus);
    cudaGetSymbolAddress((void**)&fusb,   g_fusb);

    const float* NUL = (const float*)0;
    float* FNUL = (float*)0;
    __nv_bfloat16* BNUL = (__nv_bfloat16*)0;

    const int SMEMT = 3 * (64 * 36 + 32 * 68) * 4;  // 53760
    cudaFuncSetAttribute(k_gemmt, cudaFuncAttributeMaxDynamicSharedMemorySize, SMEMT);

    static cudaStream_t gs[NGRP - 1];
    static cudaEvent_t  evFork, evJoin[NGRP - 1];
    static int s_init = 0;
    if (!s_init) {
        for (int i = 0; i < NGRP - 1; i++)
            cudaStreamCreateWithFlags(&gs[i], cudaStreamNonBlocking);
        cudaEventCreateWithFlags(&evFork, cudaEventDisableTiming);
        for (int i = 0; i < NGRP - 1; i++)
            cudaEventCreateWithFlags(&evJoin[i], cudaEventDisableTiming);
        s_init = 1;
    }

    // ---- setup (main stream) ----
    const int NSET = 64 * 2560 + 512 * 512 + 512 * 2048 + 2048 * 512 + 512 * 448
                   + OBS * NB * 32;
    k_setup<<<(NSET + 255) / 256, 256>>>(Wqkv, Wo, Wff1, Wff2, Wfus, obs, Wemb, bemb);
    k_gemms<<<dim3(24, 40, 3), 256>>>(feat, Wqkv, bqkv, Wfus, bfus);
    k_initprep<<<BMT, 128>>>(obs, Wemb, bemb, loc, feat, Wfus);

    cudaEventRecord(evFork, 0);
    for (int i = 0; i < NGRP - 1; i++) cudaStreamWaitEvent(gs[i], evFork, 0);

    const int EKLD = HOR * 1024;
    const int GY = GROWS / 64;   // 8
    for (int g = 0; g < NGRP; g++) {
        cudaStream_t st = (g == 0) ? (cudaStream_t)0 : gs[g - 1];
        const int off = g * GROWS;
        float* Eg   = E + (size_t)off * 64;
        float* Qg   = QKVC + (size_t)off * 1536;
        float* ctxg = ctx + (size_t)off * 512;
        float* wog  = wo + (size_t)off * 512;
        float* wobg = wob + (size_t)off * 512;
        float* xlg  = xlast + (size_t)off * 512;
        float* h1g  = h1 + (size_t)off * 512;
        float* ff1g = ff1 + (size_t)off * 2048;
        float* ff2g = ff2 + (size_t)off * 512;
        float* f2bg = ff2b + (size_t)off * 512;
        float* h2g  = h2 + (size_t)off * 512;
        float* fusg = fus + (size_t)off * 448;
        float* fubg = fusb + (size_t)off * 448;
        float* rfg  = rowfus + (size_t)off * 448;
        __nv_bfloat16* eKVg = eKV + (size_t)off * EKLD;

        // standalone QKVC for f=OBS only (eKV goes to unused dummy slot HOR-1)
        k_gemmt<<<dim3(40, GY), 256, SMEMT, st>>>(Eg, 64, Wcat, 2560, Qg, 1536, 64,
                                                  NUL, cfeat, 256, 1536, 0, 0, FNUL,
                                                  eKVg, 1536, (HOR - 1) * 1024, EKLD);
        for (int f = OBS; f < OBS + HOR; f++) {
            k_attn<<<GROWS, 256, 0, st>>>(f, off);
            k_gemmt<<<dim3(8, GY, 2), 256, SMEMT, st>>>(ctxg, 512, Wor, 512, wog, 512, 256,
                                                        bo, NUL, 1, 0, 0, 0, wobg,
                                                        BNUL, 1 << 30, 0, 0);
            k_ln<<<GROWS / 8, 256, 0, st>>>(xlg, wog, wobg, ln1g, ln1b, h1g);
            k_gemmt<<<dim3(32, GY), 256, SMEMT, st>>>(h1g, 512, Wff1r, 2048, ff1g, 2048, 512,
                                                      bff1, NUL, 1, 0, 1, 1, FNUL,
                                                      BNUL, 1 << 30, 0, 0);
            k_gemmt<<<dim3(8, GY, 2), 256, SMEMT, st>>>(ff1g, 2048, Wff2r, 512, ff2g, 512, 1024,
                                                        bff2, NUL, 1, 0, 0, 0, f2bg,
                                                        BNUL, 1 << 30, 0, 0);
            k_ln<<<GROWS / 8, 256, 0, st>>>(h1g, ff2g, f2bg, ln2g, ln2b, h2g);
            k_gemmt<<<dim3(7, GY, 2), 256, SMEMT, st>>>(h2g, 512, Wfusr, 448, fusg, 448, 256,
                                                        NUL, rfg, GROWS, 448, 0, 0, fubg,
                                                        BNUL, 1 << 30, 0, 0);
            // fused: out + emb + prep(f+1) + QKVC(f+1) + eKV[f]
            k_stepq<<<GROWS / 16, 256, 0, st>>>(Wout, bout, Wemb, bemb, loc, feat, Wfus,
                                                outp, f, off);
        }
    }

    for (int i = 0; i < NGRP - 1; i++) {
        cudaEventRecord(evJoin[i], gs[i]);
        cudaStreamWaitEvent((cudaStream_t)0, evJoin[i], 0);
    }
    (void)in_sizes; (void)n_in; (void)out_size;
}

// round 15
// speedup vs baseline: 1.1804x; 1.1176x over previous
#include <cuda_runtime.h>
#include <cuda_bf16.h>
#include <math.h>

#define NB    256
#define NM    6
#define INC   448
#define EMB   32
#define OBS   20
#define HOR   30
#define DD    512
#define DFF   2048
#define BMT   1536     // NB*NM
#define NGRP  3        // 2 created streams + default: passes the memory guard
#define GROWS (BMT / NGRP)   // 512 rows per group

// ------------------------- scratch (static device globals) -------------------------
__device__ __align__(256) float g_cfeat[NB*1536];
__device__ __align__(256) float g_cffus[NB*448];
__device__ __align__(256) float g_Wcat[64*2560];       // tf32; cols 1536:2560 = emb->eKV map
__device__ __align__(256) float g_Wor[512*512];
__device__ __align__(256) float g_Wff1r[512*2048];
__device__ __align__(256) float g_Wff2r[2048*512];
__device__ __align__(256) float g_Wfusr[512*448];
__device__ __align__(256) float g_eobs[OBS*NB*32];     // rows ordered [b][l]
__device__ __align__(256) __nv_bfloat16 g_eKVo[(size_t)NB*OBS*1024];   // [b][l][1024]
__device__ __align__(256) __nv_bfloat16 g_eKV[(size_t)BMT*HOR*1024];   // [bm][slot][1024]
__device__ __align__(256) float g_E[BMT*64];
__device__ __align__(256) float g_xlast[BMT*DD];
__device__ __align__(256) float g_rowfus[BMT*448];
__device__ __align__(256) float g_QKVC[BMT*1536];
__device__ __align__(256) float g_ctx[BMT*DD];
__device__ __align__(256) float g_wo[BMT*DD];
__device__ __align__(256) float g_wob[BMT*DD];
__device__ __align__(256) float g_h1[BMT*DD];
__device__ __align__(256) float g_ff1[BMT*DFF];
__device__ __align__(256) float g_ff2[BMT*DD];
__device__ __align__(256) float g_ff2b[BMT*DD];
__device__ __align__(256) float g_fus[BMT*448];
__device__ __align__(256) float g_fusb[BMT*448];

// --------------------------- TF32 helpers ----------------------------------------
__device__ __forceinline__ unsigned f2tf(float x) {
    unsigned u;
    asm("cvt.rna.tf32.f32 %0, %1;" : "=r"(u) : "f"(x));
    return u;
}
__device__ __forceinline__ float tfr(float x) { return __uint_as_float(f2tf(x)); }

__device__ __forceinline__ void mma8(float* d, const unsigned* a, const unsigned* b) {
    asm volatile(
        "mma.sync.aligned.m16n8k8.row.col.f32.tf32.tf32.f32 "
        "{%0,%1,%2,%3}, {%4,%5,%6,%7}, {%8,%9}, {%0,%1,%2,%3};"
        : "+f"(d[0]), "+f"(d[1]), "+f"(d[2]), "+f"(d[3])
        : "r"(a[0]), "r"(a[1]), "r"(a[2]), "r"(a[3]), "r"(b[0]), "r"(b[1]));
}

// ============ TF32 GEMM: 64x64 tile, 3-stage cp.async (tf32-pre-rounded) ==========
// gridDim.z==2 -> split-K: z=1 does upper K half into C2 (no bias/rowadd).
// EK != null: blocks with col0 >= ekcol write bf16 to EK[r*ekld + ekoff + (c-ekcol)].
__global__ void k_gemmt(const float* __restrict__ A, int lda,
                        const float* __restrict__ Bm, int ldb,
                        float* __restrict__ C, int ldc, int K,
                        const float* __restrict__ bias,
                        const float* __restrict__ rowadd, int ramod, int ldra,
                        int relu, int otf32, float* __restrict__ C2,
                        __nv_bfloat16* __restrict__ EK, int ekcol, int ekoff, int ekld)
{
    const int BPAD = 68, ASZ = 64 * 36, BSZ = 32 * BPAD;
    extern __shared__ float sm[];
    float* AsB = sm;            // 3 stages
    float* BsB = sm + 3 * ASZ;

    if (blockIdx.z) { A += K; Bm += (size_t)K * ldb; C = C2; bias = 0; rowadd = 0; }

    const int row0 = blockIdx.y * 64, col0 = blockIdx.x * 64;
    const int tid = threadIdx.x, warp = tid >> 5, lane = tid & 31;
    const int wm = warp >> 2, wn = warp & 3;
    const int l4 = lane >> 2, lm4 = lane & 3;
    const int ar = tid >> 3, akq = (tid & 7) * 4;
    const int brow0 = tid >> 4, bc4 = (tid & 15) * 4;

    float acc[2][2][4] = {};

    auto load = [&](int k0, int s) {
        float* as = AsB + s * ASZ;
        float* bs = BsB + s * BSZ;
#pragma unroll
        for (int i = 0; i < 2; i++) {
            unsigned d = (unsigned)__cvta_generic_to_shared(as + (ar + i * 32) * 36 + akq);
            const float* g = A + (size_t)(row0 + ar + i * 32) * lda + k0 + akq;
            asm volatile("cp.async.cg.shared.global [%0],[%1],16;\n" :: "r"(d), "l"(g));
        }
#pragma unroll
        for (int i = 0; i < 2; i++) {
            int row = brow0 + i * 16;
            unsigned d = (unsigned)__cvta_generic_to_shared(bs + row * BPAD + bc4);
            const float* g = Bm + (size_t)(k0 + row) * ldb + col0 + bc4;
            asm volatile("cp.async.cg.shared.global [%0],[%1],16;\n" :: "r"(d), "l"(g));
        }
        asm volatile("cp.async.commit_group;\n");
    };

    const int nslab = K >> 5;
    load(0, 0);
    if (nslab > 1) load(32, 1); else asm volatile("cp.async.commit_group;\n");

    for (int k = 0; k < nslab; k++) {
        asm volatile("cp.async.wait_group 1;\n");
        __syncthreads();
        if (k + 2 < nslab) load((k + 2) * 32, (k + 2) % 3);
        else               asm volatile("cp.async.commit_group;\n");
        const float* as = AsB + (k % 3) * ASZ;
        const float* bs = BsB + (k % 3) * BSZ;
#pragma unroll
        for (int ks = 0; ks < 4; ks++) {
            const int kk = ks * 8;
            unsigned a[2][4], b[2][2];
#pragma unroll
            for (int mi = 0; mi < 2; mi++) {
                int mb = wm * 32 + mi * 16 + l4;
                a[mi][0] = __float_as_uint(as[mb * 36 + kk + lm4]);
                a[mi][1] = __float_as_uint(as[(mb + 8) * 36 + kk + lm4]);
                a[mi][2] = __float_as_uint(as[mb * 36 + kk + lm4 + 4]);
                a[mi][3] = __float_as_uint(as[(mb + 8) * 36 + kk + lm4 + 4]);
            }
#pragma unroll
            for (int nj = 0; nj < 2; nj++) {
                int nb = wn * 16 + nj * 8 + l4;
                b[nj][0] = __float_as_uint(bs[(kk + lm4) * BPAD + nb]);
                b[nj][1] = __float_as_uint(bs[(kk + lm4 + 4) * BPAD + nb]);
            }
#pragma unroll
            for (int mi = 0; mi < 2; mi++)
#pragma unroll
                for (int nj = 0; nj < 2; nj++)
                    mma8(acc[mi][nj], a[mi], b[nj]);
        }
        __syncthreads();
    }

    const bool ekreg = (EK != 0) && (col0 >= ekcol);
#pragma unroll
    for (int mi = 0; mi < 2; mi++) {
        const int rb = row0 + wm * 32 + mi * 16 + l4;
#pragma unroll
        for (int nj = 0; nj < 2; nj++) {
            const int c = col0 + wn * 16 + nj * 8 + lm4 * 2;
#pragma unroll
            for (int h = 0; h < 2; h++) {
                const int r = rb + h * 8;
                float v0 = acc[mi][nj][h * 2 + 0];
                float v1 = acc[mi][nj][h * 2 + 1];
                if (ekreg) {
                    *(__nv_bfloat162*)(EK + (size_t)r * ekld + ekoff + (c - ekcol)) =
                        __floats2bfloat162_rn(v0, v1);
                    continue;
                }
                if (bias) { v0 += bias[c]; v1 += bias[c + 1]; }
                if (rowadd) {
                    const float* ra = rowadd + (size_t)(r % ramod) * ldra + c;
                    v0 += ra[0]; v1 += ra[1];
                }
                if (relu) { v0 = fmaxf(v0, 0.f); v1 = fmaxf(v1, 0.f); }
                if (otf32) { v0 = tfr(v0); v1 = tfr(v1); }
                *(float2*)(C + (size_t)r * ldc + c) = make_float2(v0, v1);
            }
        }
    }
}

// ====== LN-fused GEMM: C = (tf32(LN(x1+x2+x3)*g+b)) @ W (+bias)(+rowadd)(relu) ====
// A rows live at (row0+r)*512 in x1/x2/x3 (full rows, K=512 total).
// gridDim.z==2 -> split-K halves of Khalf; stats always over the full 512 row.
// h1out != null: blocks (x==0, z==0) also materialize the tf32 LN rows.
__global__ void k_gemmln(const float* __restrict__ x1, const float* __restrict__ x2,
                         const float* __restrict__ x3,
                         const float* __restrict__ gg, const float* __restrict__ bbv,
                         const float* __restrict__ W, int ldb,
                         float* __restrict__ C, int ldc, int Khalf,
                         const float* __restrict__ bias,
                         const float* __restrict__ rowadd, int ramod, int ldra,
                         int relu, int otf32, float* __restrict__ C2,
                         float* __restrict__ h1out)
{
    const int BPAD = 68, ASZ = 64 * 36, BSZ = 32 * BPAD;
    extern __shared__ float sm[];
    float* As2 = sm;                       // 2 stages
    float* Bs2 = sm + 2 * ASZ;             // 2 stages
    float* smu = sm + 2 * ASZ + 2 * BSZ;   // 64
    float* srs = smu + 64;                 // 64

    int kbase = 0;
    if (blockIdx.z) { kbase = Khalf; C = C2; bias = 0; rowadd = 0; }

    const int row0 = blockIdx.y * 64, col0 = blockIdx.x * 64;
    const int tid = threadIdx.x, warp = tid >> 5, lane = tid & 31;
    const int wm = warp >> 2, wn = warp & 3;
    const int l4 = lane >> 2, lm4 = lane & 3;
    const int ar = tid >> 3, akq = (tid & 7) * 4;
    const int brow0 = tid >> 4, bc4 = (tid & 15) * 4;
    const bool wh1 = (h1out != 0) && (blockIdx.x == 0) && (blockIdx.z == 0);

    // ---- stats prologue (two-pass, mirrors k_ln exactly) ----
#pragma unroll 1
    for (int rr = 0; rr < 8; rr++) {
        int row = warp * 8 + rr;
        size_t base = (size_t)(row0 + row) * 512;
        float sum = 0.f;
#pragma unroll
        for (int j = 0; j < 16; j++) {
            int e = lane + j * 32;
            sum += x1[base + e] + x2[base + e] + x3[base + e];
        }
#pragma unroll
        for (int o = 16; o; o >>= 1) sum += __shfl_xor_sync(0xffffffffu, sum, o);
        float mu = sum * (1.f / 512.f);
        float var = 0.f;
#pragma unroll
        for (int j = 0; j < 16; j++) {
            int e = lane + j * 32;
            float d = x1[base + e] + x2[base + e] + x3[base + e] - mu;
            var += d * d;
        }
#pragma unroll
        for (int o = 16; o; o >>= 1) var += __shfl_xor_sync(0xffffffffu, var, o);
        if (lane == 0) {
            smu[row] = mu;
            srs[row] = rsqrtf(var * (1.f / 512.f) + 1e-5f);
        }
    }
    __syncthreads();

    float acc[2][2][4] = {};
    float4 px1[2], px2[2], px3[2];

    auto loadA = [&](int k0) {
#pragma unroll
        for (int i = 0; i < 2; i++) {
            size_t base = (size_t)(row0 + ar + i * 32) * 512 + kbase + k0 + akq;
            px1[i] = *(const float4*)(x1 + base);
            px2[i] = *(const float4*)(x2 + base);
            px3[i] = *(const float4*)(x3 + base);
        }
    };
    auto loadB = [&](int k0, int s) {
        float* bs = Bs2 + s * BSZ;
#pragma unroll
        for (int i = 0; i < 2; i++) {
            int row = brow0 + i * 16;
            unsigned d = (unsigned)__cvta_generic_to_shared(bs + row * BPAD + bc4);
            const float* g = W + (size_t)(kbase + k0 + row) * ldb + col0 + bc4;
            asm volatile("cp.async.cg.shared.global [%0],[%1],16;\n" :: "r"(d), "l"(g));
        }
        asm volatile("cp.async.commit_group;\n");
    };

    const int nslab = Khalf >> 5;
    loadA(0);
    loadB(0, 0);

    for (int k = 0; k < nslab; k++) {
        // transform + store A slab k
        float* as = As2 + (k & 1) * ASZ;
        const int kc = kbase + k * 32 + akq;
        float4 g4 = *(const float4*)(gg + kc);
        float4 b4 = *(const float4*)(bbv + kc);
#pragma unroll
        for (int i = 0; i < 2; i++) {
            int r = ar + i * 32;
            float mu = smu[r], rs = srs[r];
            float a0 = tfr((px1[i].x + px2[i].x + px3[i].x - mu) * rs * g4.x + b4.x);
            float a1 = tfr((px1[i].y + px2[i].y + px3[i].y - mu) * rs * g4.y + b4.y);
            float a2 = tfr((px1[i].z + px2[i].z + px3[i].z - mu) * rs * g4.z + b4.z);
            float a3 = tfr((px1[i].w + px2[i].w + px3[i].w - mu) * rs * g4.w + b4.w);
            float* p = &as[r * 36 + akq];
            p[0] = a0; p[1] = a1; p[2] = a2; p[3] = a3;
            if (wh1)
                *(float4*)(h1out + (size_t)(row0 + r) * 512 + kc) =
                    make_float4(a0, a1, a2, a3);
        }
        if (k + 1 < nslab) { loadA((k + 1) * 32); loadB((k + 1) * 32, (k + 1) & 1); }
        else               asm volatile("cp.async.commit_group;\n");
        asm volatile("cp.async.wait_group 1;\n");
        __syncthreads();
        const float* bs = Bs2 + (k & 1) * BSZ;
#pragma unroll
        for (int ks = 0; ks < 4; ks++) {
            const int kk = ks * 8;
            unsigned a[2][4], b[2][2];
#pragma unroll
            for (int mi = 0; mi < 2; mi++) {
                int mb = wm * 32 + mi * 16 + l4;
                a[mi][0] = __float_as_uint(as[mb * 36 + kk + lm4]);
                a[mi][1] = __float_as_uint(as[(mb + 8) * 36 + kk + lm4]);
                a[mi][2] = __float_as_uint(as[mb * 36 + kk + lm4 + 4]);
                a[mi][3] = __float_as_uint(as[(mb + 8) * 36 + kk + lm4 + 4]);
            }
#pragma unroll
            for (int nj = 0; nj < 2; nj++) {
                int nb = wn * 16 + nj * 8 + l4;
                b[nj][0] = __float_as_uint(bs[(kk + lm4) * BPAD + nb]);
                b[nj][1] = __float_as_uint(bs[(kk + lm4 + 4) * BPAD + nb]);
            }
#pragma unroll
            for (int mi = 0; mi < 2; mi++)
#pragma unroll
                for (int nj = 0; nj < 2; nj++)
                    mma8(acc[mi][nj], a[mi], b[nj]);
        }
        __syncthreads();
    }

#pragma unroll
    for (int mi = 0; mi < 2; mi++) {
        const int rb = row0 + wm * 32 + mi * 16 + l4;
#pragma unroll
        for (int nj = 0; nj < 2; nj++) {
            const int c = col0 + wn * 16 + nj * 8 + lm4 * 2;
#pragma unroll
            for (int h = 0; h < 2; h++) {
                const int r = rb + h * 8;
                float v0 = acc[mi][nj][h * 2 + 0];
                float v1 = acc[mi][nj][h * 2 + 1];
                if (bias) { v0 += bias[c]; v1 += bias[c + 1]; }
                if (rowadd) {
                    const float* ra = rowadd + (size_t)(r % ramod) * ldra + c;
                    v0 += ra[0]; v1 += ra[1];
                }
                if (relu) { v0 = fmaxf(v0, 0.f); v1 = fmaxf(v1, 0.f); }
                if (otf32) { v0 = tfr(v0); v1 = tfr(v1); }
                *(float2*)(C + (size_t)r * ldc + c) = make_float2(v0, v1);
            }
        }
    }
}

// --------------- legacy converting GEMM core (setup paths only) -------------------
__device__ __forceinline__ void gemm0_body(const float* __restrict__ A, int lda,
                                           const float* __restrict__ Bm, int ldb,
                                           void* __restrict__ Cv, int ldc, int K,
                                           const float* __restrict__ bias, int obf16)
{
    __shared__ __align__(16) unsigned As[128 * 36];
    __shared__ __align__(16) unsigned Bs[32 * 68];
    const int row0 = blockIdx.y * 128, col0 = blockIdx.x * 64;
    const int tid = threadIdx.x;
    const int warp = tid >> 5, lane = tid & 31;
    const int wm = warp >> 1, wn = warp & 1;
    const int l4 = lane >> 2, lm4 = lane & 3;
    const int ar = tid >> 3, akq = (tid & 7) * 4;
    const int br = tid >> 4, bcq = (tid & 15) * 4;

    float acc[2][4][4] = {};
    float4 pa[4], pb[2];
#pragma unroll
    for (int it = 0; it < 4; it++)
        pa[it] = *(const float4*)(A + (size_t)(row0 + ar + it * 32) * lda + akq);
#pragma unroll
    for (int it = 0; it < 2; it++)
        pb[it] = *(const float4*)(Bm + (size_t)(br + it * 16) * ldb + col0 + bcq);

    for (int k0 = 0; k0 < K; k0 += 32) {
#pragma unroll
        for (int it = 0; it < 4; it++) {
            unsigned* p = &As[(ar + it * 32) * 36 + akq];
            p[0] = f2tf(pa[it].x); p[1] = f2tf(pa[it].y);
            p[2] = f2tf(pa[it].z); p[3] = f2tf(pa[it].w);
        }
#pragma unroll
        for (int it = 0; it < 2; it++) {
            unsigned* p = &Bs[(br + it * 16) * 68 + bcq];
            p[0] = f2tf(pb[it].x); p[1] = f2tf(pb[it].y);
            p[2] = f2tf(pb[it].z); p[3] = f2tf(pb[it].w);
        }
        __syncthreads();
        if (k0 + 32 < K) {
#pragma unroll
            for (int it = 0; it < 4; it++)
                pa[it] = *(const float4*)(A + (size_t)(row0 + ar + it * 32) * lda + k0 + 32 + akq);
#pragma unroll
            for (int it = 0; it < 2; it++)
                pb[it] = *(const float4*)(Bm + (size_t)(k0 + 32 + br + it * 16) * ldb + col0 + bcq);
        }
#pragma unroll
        for (int ks = 0; ks < 4; ks++) {
            const int kk = ks * 8;
            unsigned a[2][4], b[4][2];
#pragma unroll
            for (int mi = 0; mi < 2; mi++) {
                int mb = wm * 32 + mi * 16 + l4;
                a[mi][0] = As[mb * 36 + kk + lm4];
                a[mi][1] = As[(mb + 8) * 36 + kk + lm4];
                a[mi][2] = As[mb * 36 + kk + lm4 + 4];
                a[mi][3] = As[(mb + 8) * 36 + kk + lm4 + 4];
            }
#pragma unroll
            for (int nj = 0; nj < 4; nj++) {
                int nb = wn * 32 + nj * 8 + l4;
                b[nj][0] = Bs[(kk + lm4) * 68 + nb];
                b[nj][1] = Bs[(kk + lm4 + 4) * 68 + nb];
            }
#pragma unroll
            for (int mi = 0; mi < 2; mi++)
#pragma unroll
                for (int nj = 0; nj < 4; nj++)
                    mma8(acc[mi][nj], a[mi], b[nj]);
        }
        __syncthreads();
    }
#pragma unroll
    for (int mi = 0; mi < 2; mi++) {
        const int rb = row0 + wm * 32 + mi * 16 + l4;
#pragma unroll
        for (int nj = 0; nj < 4; nj++) {
            const int c = col0 + wn * 32 + nj * 8 + lm4 * 2;
#pragma unroll
            for (int h = 0; h < 2; h++) {
                const int r = rb + h * 8;
                float v0 = acc[mi][nj][h * 2 + 0];
                float v1 = acc[mi][nj][h * 2 + 1];
                if (bias) { v0 += bias[c]; v1 += bias[c + 1]; }
                if (obf16) {
                    *(__nv_bfloat162*)((__nv_bfloat16*)Cv + (size_t)r * ldc + c) =
                        __floats2bfloat162_rn(v0, v1);
                } else {
                    *(float2*)((float*)Cv + (size_t)r * ldc + c) = make_float2(v0, v1);
                }
            }
        }
    }
}

// setup GEMMs, z-dispatch: z=0 cfeat, z=1 cffus, z=2 eKVo
__global__ void k_gemms(const float* __restrict__ feat,
                        const float* __restrict__ Wqkv, const float* __restrict__ bqkv,
                        const float* __restrict__ Wfus, const float* __restrict__ bfus)
{
    if (blockIdx.z == 0) {
        if (blockIdx.x >= 24 || blockIdx.y >= 2) return;
        gemm0_body(feat, 448, Wqkv + 64 * 1536, 1536, g_cfeat, 1536, 448, bqkv, 0);
    } else if (blockIdx.z == 1) {
        if (blockIdx.x >= 7 || blockIdx.y >= 2) return;
        gemm0_body(feat, 448, Wfus + 519 * 448, 448, g_cffus, 448, 448, bfus, 0);
    } else {
        if (blockIdx.x >= 16 || blockIdx.y >= 40) return;
        gemm0_body(g_eobs, 32, Wqkv + 512, 1536, g_eKVo, 1024, 32, (const float*)0, 1);
    }
}

// ---------------- one-time: weights + Wcat + obs embeddings -----------------------
__global__ void k_setup(const float* __restrict__ Wqkv, const float* __restrict__ Wo,
                        const float* __restrict__ Wff1, const float* __restrict__ Wff2,
                        const float* __restrict__ Wfus,
                        const float* __restrict__ obs, const float* __restrict__ Wemb,
                        const float* __restrict__ bemb)
{
    int i = blockIdx.x * 256 + threadIdx.x;
    const int N0 = 64 * 2560, N1 = 512 * 512, N2 = 512 * 2048,
              N3 = 2048 * 512, N4 = 512 * 448, N5 = OBS * NB * 32;
    if (i < N0) {
        int r = i / 2560, c = i - r * 2560;
        float v;
        if (c < 1536)
            v = (r < 32) ? Wqkv[(32 + r) * 1536 + c]
                         : ((c < 512) ? Wqkv[(r - 32) * 1536 + c] : 0.f);
        else
            v = (r < 32) ? 0.f : Wqkv[(r - 32) * 1536 + 512 + (c - 1536)];
        g_Wcat[i] = tfr(v);
        return;
    }
    i -= N0;
    if (i < N1) { g_Wor[i]   = tfr(Wo[i]);   return; } i -= N1;
    if (i < N2) { g_Wff1r[i] = tfr(Wff1[i]); return; } i -= N2;
    if (i < N3) { g_Wff2r[i] = tfr(Wff2[i]); return; } i -= N3;
    if (i < N4) { g_Wfusr[i] = tfr(Wfus[i]); return; } i -= N4;
    if (i < N5) {
        int d = i >> 5, t = i & 31;
        int b = d / OBS, l = d - b * OBS;
        float o0 = obs[(l * NB + b) * 2 + 0];
        float o1 = obs[(l * NB + b) * 2 + 1];
        g_eobs[i] = fmaxf(o0 * Wemb[t] + o1 * Wemb[32 + t] + bemb[t], 0.f);
    }
}

__global__ void k_initprep(const float* __restrict__ obs, const float* __restrict__ Wemb,
                           const float* __restrict__ bemb,
                           const float* __restrict__ loc, const float* __restrict__ feat,
                           const float* __restrict__ Wfus)
{
    int bm = blockIdx.x, tid = threadIdx.x;
    int b = bm & 255, m = bm >> 8;
    float lx = obs[((OBS - 1) * NB + b) * 2 + 0];
    float ly = obs[((OBS - 1) * NB + b) * 2 + 1];
    __shared__ float se[32], ex[32];
    if (tid < 32)
        se[tid] = fmaxf(lx * Wemb[tid] + ly * Wemb[32 + tid] + bemb[tid], 0.f);
    float gx = loc[(b * NM + m) * 2 + 0], gy = loc[(b * NM + m) * 2 + 1];
    float dx = gx - lx, dy = gy - ly;
    float t = (float)OBS;
    __syncthreads();
    if (tid < 32) {
        float v;
        if (tid < 8)       v = (tid & 1) ? gy : gx;
        else if (tid < 16) v = (tid & 1) ? ly : lx;
        else if (tid < 24) v = (tid & 1) ? dy : dx;
        else               v = t;
        ex[tid] = v;
        g_E[bm * 64 + tid] = tfr(v);
        g_E[bm * 64 + 32 + tid] = tfr(se[tid]);
    }
    __syncthreads();
    for (int c = tid; c < 512; c += 128) {
        float v;
        if (c < 32)      v = se[c];
        else if (c < 64) v = ex[c - 32];
        else             v = feat[b * INC + (c - 64)];
        g_xlast[bm * 512 + c] = v;
    }
    for (int c = tid; c < 448; c += 128) {
        float v = g_cffus[b * 448 + c];
        v += lx * Wfus[(512 + 0) * 448 + c];
        v += ly * Wfus[(512 + 1) * 448 + c];
        v += gx * Wfus[(512 + 2) * 448 + c];
        v += gy * Wfus[(512 + 3) * 448 + c];
        v += dx * Wfus[(512 + 4) * 448 + c];
        v += dy * Wfus[(512 + 5) * 448 + c];
        v += t  * Wfus[(512 + 6) * 448 + c];
        g_rowfus[bm * 448 + c] = v;
    }
}

// ------------------------- per-step attention (bm0 = group row base) ---------------
__global__ void k_attn(int f, int bm0)
{
    int bm = blockIdx.x + bm0;
    int tid = threadIdx.x, w = tid >> 5, lane = tid & 31;
    int b = bm & 255;
    const float* qp = g_QKVC + (size_t)bm * 1536 + w * 64;
    float q0 = qp[2 * lane], q1 = qp[2 * lane + 1];
    const float* ckp = qp + 512;
    float s = q0 * ckp[2 * lane] + q1 * ckp[2 * lane + 1];
#pragma unroll
    for (int o = 16; o; o >>= 1) s += __shfl_xor_sync(0xffffffffu, s, o);
    const float qdot = s;
    __shared__ float sp[8][56];
    const int off = w * 64 + 2 * lane;
    const __nv_bfloat16* ob = g_eKVo + (size_t)b * OBS * 1024 + off;
    const __nv_bfloat16* rbp = g_eKV + (size_t)bm * HOR * 1024 + off;
    const int fr = f - OBS;
    for (int l = 0; l < OBS; l++) {
        float2 kf = __bfloat1622float2(*(const __nv_bfloat162*)(ob + l * 1024));
        float d = q0 * kf.x + q1 * kf.y;
#pragma unroll
        for (int o = 16; o; o >>= 1) d += __shfl_xor_sync(0xffffffffu, d, o);
        if (lane == 0) sp[w][l] = (d + qdot) * 0.125f;
    }
    for (int l = 0; l < fr; l++) {
        float2 kf = __bfloat1622float2(*(const __nv_bfloat162*)(rbp + l * 1024));
        float d = q0 * kf.x + q1 * kf.y;
#pragma unroll
        for (int o = 16; o; o >>= 1) d += __shfl_xor_sync(0xffffffffu, d, o);
        if (lane == 0) sp[w][OBS + l] = (d + qdot) * 0.125f;
    }
    __syncwarp();
    float mx = -1e30f;
    if (lane < f)      mx = sp[w][lane];
    if (lane + 32 < f) mx = fmaxf(mx, sp[w][lane + 32]);
#pragma unroll
    for (int o = 16; o; o >>= 1) mx = fmaxf(mx, __shfl_xor_sync(0xffffffffu, mx, o));
    float e0 = 0.f, e1 = 0.f;
    if (lane < f)      e0 = expf(sp[w][lane] - mx);
    if (lane + 32 < f) e1 = expf(sp[w][lane + 32] - mx);
    float sum = e0 + e1;
#pragma unroll
    for (int o = 16; o; o >>= 1) sum += __shfl_xor_sync(0xffffffffu, sum, o);
    if (lane < f)      sp[w][lane] = e0;
    if (lane + 32 < f) sp[w][lane + 32] = e1;
    __syncwarp();
    float inv = 1.f / sum;
    const float* cvp = qp + 1024;
    float a0 = 0.f, a1 = 0.f;
    for (int l = 0; l < OBS; l++) {
        float p = sp[w][l];
        float2 vf = __bfloat1622float2(*(const __nv_bfloat162*)(ob + 512 + l * 1024));
        a0 += p * vf.x; a1 += p * vf.y;
    }
    for (int l = 0; l < fr; l++) {
        float p = sp[w][OBS + l];
        float2 vf = __bfloat1622float2(*(const __nv_bfloat162*)(rbp + 512 + l * 1024));
        a0 += p * vf.x; a1 += p * vf.y;
    }
    float* op = g_ctx + (size_t)bm * 512 + off;
    *(float2*)op = make_float2(tfr(cvp[2 * lane] + a0 * inv),
                               tfr(cvp[2 * lane + 1] + a1 * inv));
}

// ---- fused per-step epilogue: out + emb + prep for step f+1 ---------------------
__global__ void k_step(const float* __restrict__ Wout, const float* __restrict__ bout,
                       const float* __restrict__ Wemb, const float* __restrict__ bemb,
                       const float* __restrict__ loc, const float* __restrict__ feat,
                       const float* __restrict__ Wfus,
                       float* __restrict__ dout, int f, int bm0)
{
    int bm = blockIdx.x + bm0, tid = threadIdx.x;
    int w = tid >> 5, lane = tid & 31;
    int b = bm & 255, m = bm >> 8;
    __shared__ float r0[4], r1[4];
    __shared__ float se[32], ex[32];

    float s0 = 0.f, s1 = 0.f;
    const float* fp  = g_fus  + (size_t)bm * 448;
    const float* fpb = g_fusb + (size_t)bm * 448;
    for (int c = tid; c < 448; c += 128) {
        float v = fp[c] + fpb[c];
        s0 += v * Wout[c * 2 + 0];
        s1 += v * Wout[c * 2 + 1];
    }
#pragma unroll
    for (int o = 16; o; o >>= 1) {
        s0 += __shfl_xor_sync(0xffffffffu, s0, o);
        s1 += __shfl_xor_sync(0xffffffffu, s1, o);
    }
    if (lane == 0) { r0[w] = s0; r1[w] = s1; }
    __syncthreads();
    float o0 = r0[0] + r0[1] + r0[2] + r0[3] + bout[0];
    float o1 = r1[0] + r1[1] + r1[2] + r1[3] + bout[1];

    if (tid < 32)
        se[tid] = fmaxf(o0 * Wemb[tid] + o1 * Wemb[32 + tid] + bemb[tid], 0.f);
    if (tid == 0) {
        int t = f - OBS;
        dout[b * (NM * HOR * 2) + m * (HOR * 2) + t * 2 + 0] = o0;
        dout[b * (NM * HOR * 2) + m * (HOR * 2) + t * 2 + 1] = o1;
    }
    __syncthreads();

    int fn = f + 1;
    if (fn < OBS + HOR) {
        float gx = loc[(b * NM + m) * 2 + 0], gy = loc[(b * NM + m) * 2 + 1];
        float dx = gx - o0, dy = gy - o1;
        float t = (float)fn;
        if (tid < 32) {
            float v;
            if (tid < 8)       v = (tid & 1) ? gy : gx;
            else if (tid < 16) v = (tid & 1) ? o1 : o0;
            else if (tid < 24) v = (tid & 1) ? dy : dx;
            else               v = t;
            ex[tid] = v;
            g_E[bm * 64 + tid] = tfr(v);
            g_E[bm * 64 + 32 + tid] = tfr(se[tid]);
        }
        __syncthreads();
        for (int c = tid; c < 512; c += 128) {
            float v;
            if (c < 32)      v = se[c];
            else if (c < 64) v = ex[c - 32];
            else             v = feat[b * INC + (c - 64)];
            g_xlast[bm * 512 + c] = v;
        }
        for (int c = tid; c < 448; c += 128) {
            float v = g_cffus[b * 448 + c];
            v += o0 * Wfus[(512 + 0) * 448 + c];
            v += o1 * Wfus[(512 + 1) * 448 + c];
            v += gx * Wfus[(512 + 2) * 448 + c];
            v += gy * Wfus[(512 + 3) * 448 + c];
            v += dx * Wfus[(512 + 4) * 448 + c];
            v += dy * Wfus[(512 + 5) * 448 + c];
            v += t  * Wfus[(512 + 6) * 448 + c];
            g_rowfus[bm * 448 + c] = v;
        }
    }
}

// ----------------------------------- launch ---------------------------------------
extern "C" void kernel_launch(void* const* d_in, const int* in_sizes, int n_in,
                              void* d_out, int out_size)
{
    const float* feat = (const float*)d_in[0];
    const float* loc  = (const float*)d_in[1];
    const float* obs  = (const float*)d_in[2];
    const float* Wemb = (const float*)d_in[3];
    const float* bemb = (const float*)d_in[4];
    const float* Wqkv = (const float*)d_in[5];
    const float* bqkv = (const float*)d_in[6];
    const float* Wo   = (const float*)d_in[7];
    const float* bo   = (const float*)d_in[8];
    const float* Wff1 = (const float*)d_in[9];
    const float* bff1 = (const float*)d_in[10];
    const float* Wff2 = (const float*)d_in[11];
    const float* bff2 = (const float*)d_in[12];
    const float* ln1g = (const float*)d_in[13];
    const float* ln1b = (const float*)d_in[14];
    const float* ln2g = (const float*)d_in[15];
    const float* ln2b = (const float*)d_in[16];
    const float* Wfus = (const float*)d_in[17];
    const float* bfus = (const float*)d_in[18];
    const float* Wout = (const float*)d_in[19];
    const float* bout = (const float*)d_in[20];
    float* outp = (float*)d_out;

    float *cfeat, *E, *xlast, *rowfus, *QKVC, *ctx, *wo, *wob, *h1, *ff1, *ff2,
          *ff2b, *fus, *fusb, *Wor, *Wff1r, *Wff2r, *Wfusr, *Wcat;
    __nv_bfloat16 *eKV;
    cudaGetSymbolAddress((void**)&cfeat,  g_cfeat);
    cudaGetSymbolAddress((void**)&Wcat,   g_Wcat);
    cudaGetSymbolAddress((void**)&Wor,    g_Wor);
    cudaGetSymbolAddress((void**)&Wff1r,  g_Wff1r);
    cudaGetSymbolAddress((void**)&Wff2r,  g_Wff2r);
    cudaGetSymbolAddress((void**)&Wfusr,  g_Wfusr);
    cudaGetSymbolAddress((void**)&eKV,    g_eKV);
    cudaGetSymbolAddress((void**)&E,      g_E);
    cudaGetSymbolAddress((void**)&xlast,  g_xlast);
    cudaGetSymbolAddress((void**)&rowfus, g_rowfus);
    cudaGetSymbolAddress((void**)&QKVC,   g_QKVC);
    cudaGetSymbolAddress((void**)&ctx,    g_ctx);
    cudaGetSymbolAddress((void**)&wo,     g_wo);
    cudaGetSymbolAddress((void**)&wob,    g_wob);
    cudaGetSymbolAddress((void**)&h1,     g_h1);
    cudaGetSymbolAddress((void**)&ff1,    g_ff1);
    cudaGetSymbolAddress((void**)&ff2,    g_ff2);
    cudaGetSymbolAddress((void**)&ff2b,   g_ff2b);
    cudaGetSymbolAddress((void**)&fus,    g_fus);
    cudaGetSymbolAddress((void**)&fusb,   g_fusb);

    const float* NUL = (const float*)0;
    float* FNUL = (float*)0;
    __nv_bfloat16* BNUL = (__nv_bfloat16*)0;

    const int SMEMT  = 3 * (64 * 36 + 32 * 68) * 4;                  // 53760
    const int SMEMLN = (2 * 64 * 36 + 2 * 32 * 68 + 128) * 4;        // 36352
    cudaFuncSetAttribute(k_gemmt,  cudaFuncAttributeMaxDynamicSharedMemorySize, SMEMT);
    cudaFuncSetAttribute(k_gemmln, cudaFuncAttributeMaxDynamicSharedMemorySize, SMEMLN);

    static cudaStream_t gs[NGRP - 1];
    static cudaEvent_t  evFork, evJoin[NGRP - 1];
    static int s_init = 0;
    if (!s_init) {
        for (int i = 0; i < NGRP - 1; i++)
            cudaStreamCreateWithFlags(&gs[i], cudaStreamNonBlocking);
        cudaEventCreateWithFlags(&evFork, cudaEventDisableTiming);
        for (int i = 0; i < NGRP - 1; i++)
            cudaEventCreateWithFlags(&evJoin[i], cudaEventDisableTiming);
        s_init = 1;
    }

    // ---- setup (main stream) ----
    const int NSET = 64 * 2560 + 512 * 512 + 512 * 2048 + 2048 * 512 + 512 * 448
                   + OBS * NB * 32;
    k_setup<<<(NSET + 255) / 256, 256>>>(Wqkv, Wo, Wff1, Wff2, Wfus, obs, Wemb, bemb);
    k_gemms<<<dim3(24, 40, 3), 256>>>(feat, Wqkv, bqkv, Wfus, bfus);
    k_initprep<<<BMT, 128>>>(obs, Wemb, bemb, loc, feat, Wfus);

    cudaEventRecord(evFork, 0);
    for (int i = 0; i < NGRP - 1; i++) cudaStreamWaitEvent(gs[i], evFork, 0);

    const int EKLD = HOR * 1024;
    const int GY = GROWS / 64;   // 8
    for (int g = 0; g < NGRP; g++) {
        cudaStream_t st = (g == 0) ? (cudaStream_t)0 : gs[g - 1];
        const int off = g * GROWS;
        float* Eg   = E + (size_t)off * 64;
        float* Qg   = QKVC + (size_t)off * 1536;
        float* ctxg = ctx + (size_t)off * 512;
        float* wog  = wo + (size_t)off * 512;
        float* wobg = wob + (size_t)off * 512;
        float* xlg  = xlast + (size_t)off * 512;
        float* h1g  = h1 + (size_t)off * 512;
        float* ff1g = ff1 + (size_t)off * 2048;
        float* ff2g = ff2 + (size_t)off * 512;
        float* f2bg = ff2b + (size_t)off * 512;
        float* fusg = fus + (size_t)off * 448;
        float* fubg = fusb + (size_t)off * 448;
        float* rfg  = rowfus + (size_t)off * 448;
        __nv_bfloat16* eKVg = eKV + (size_t)off * EKLD;

        for (int f = OBS; f < OBS + HOR; f++) {
            int ekoff = ((f == OBS) ? (HOR - 1) : (f - 1 - OBS)) * 1024;
            // 1. QKVC + eKV (K=64)
            k_gemmt<<<dim3(40, GY), 256, SMEMT, st>>>(Eg, 64, Wcat, 2560, Qg, 1536, 64,
                                                      NUL, cfeat, 256, 1536, 0, 0, FNUL,
                                                      eKVg, 1536, ekoff, EKLD);
            // 2. attention
            k_attn<<<GROWS, 256, 0, st>>>(f, off);
            // 3. wo(+wob) = ctx @ W_o + b_o  (split-K 256+256)
            k_gemmt<<<dim3(8, GY, 2), 256, SMEMT, st>>>(ctxg, 512, Wor, 512, wog, 512, 256,
                                                        bo, NUL, 1, 0, 0, 0, wobg,
                                                        BNUL, 1 << 30, 0, 0);
            // 4. ff1 = tf32(relu(LN1(xlast+wo+wob) @ Wff1 + b)); x==0 blocks write h1
            k_gemmln<<<dim3(32, GY), 256, SMEMLN, st>>>(xlg, wog, wobg, ln1g, ln1b,
                                                        Wff1r, 2048, ff1g, 2048, 512,
                                                        bff1, NUL, 1, 0, 1, 1, FNUL, h1g);
            // 5. ff2(+ff2b) = ff1 @ Wff2 + b  (split-K 1024+1024)
            k_gemmt<<<dim3(8, GY, 2), 256, SMEMT, st>>>(ff1g, 2048, Wff2r, 512, ff2g, 512, 1024,
                                                        bff2, NUL, 1, 0, 0, 0, f2bg,
                                                        BNUL, 1 << 30, 0, 0);
            // 6. fus(+fusb) = LN2(h1+ff2+ff2b) @ Wfus + rowfus  (split-K 256+256)
            k_gemmln<<<dim3(7, GY, 2), 256, SMEMLN, st>>>(h1g, ff2g, f2bg, ln2g, ln2b,
                                                          Wfusr, 448, fusg, 448, 256,
                                                          NUL, rfg, GROWS, 448, 0, 0, fubg,
                                                          FNUL);
            // 7. out + emb + prep(f+1)
            k_step<<<GROWS, 128, 0, st>>>(Wout, bout, Wemb, bemb, loc, feat, Wfus,
                                          outp, f, off);
        }
    }

    for (int i = 0; i < NGRP - 1; i++) {
        cudaEventRecord(evJoin[i], gs[i]);
        cudaStreamWaitEvent((cudaStream_t)0, evJoin[i], 0);
    }
    (void)in_sizes; (void)n_in; (void)out_size;
}

// round 16
// speedup vs baseline: 1.2816x; 1.0857x over previous
#include <cuda_runtime.h>
#include <cuda_bf16.h>
#include <math.h>

#define NB    256
#define NM    6
#define INC   448
#define EMB   32
#define OBS   20
#define HOR   30
#define DD    512
#define DFF   2048
#define BMT   1536     // NB*NM
#define NGRP  3        // 2 created streams + default: passes the memory guard
#define GROWS (BMT / NGRP)   // 512 rows per group

// ------------------------- scratch (static device globals) -------------------------
__device__ __align__(256) float g_cfeat[NB*1536];
__device__ __align__(256) float g_cffus[NB*448];
__device__ __align__(256) float g_Wcat[64*2560];       // tf32; cols 1536:2560 = emb->eKV map
__device__ __align__(256) float g_Wor[512*512];
__device__ __align__(256) float g_Wff1r[512*2048];
__device__ __align__(256) float g_Wff2r[2048*512];
__device__ __align__(256) float g_Wfusr[512*448];
__device__ __align__(256) float g_eobs[OBS*NB*32];     // rows ordered [b][l]
__device__ __align__(256) __nv_bfloat16 g_eKVo[(size_t)NB*OBS*1024];   // [b][l][1024]
__device__ __align__(256) __nv_bfloat16 g_eKV[(size_t)BMT*HOR*1024];   // [bm][slot][1024]
__device__ __align__(256) float g_E[BMT*64];
__device__ __align__(256) float g_xlast[BMT*DD];
__device__ __align__(256) float g_rowfus[BMT*448];
__device__ __align__(256) float g_QKVC[BMT*1536];
__device__ __align__(256) float g_ctx[BMT*DD];
__device__ __align__(256) float g_wo[BMT*DD];
__device__ __align__(256) float g_wob[BMT*DD];
__device__ __align__(256) float g_h1[BMT*DD];
__device__ __align__(256) float g_ff1[BMT*DFF];
__device__ __align__(256) float g_ff2[BMT*DD];
__device__ __align__(256) float g_ff2b[BMT*DD];
__device__ __align__(256) float g_h2[BMT*DD];
__device__ __align__(256) float g_fus[BMT*448];
__device__ __align__(256) float g_fusb[BMT*448];
__device__ unsigned g_cnt1[BMT/64];   // LN1 tickets (zero-init; finalizer resets)
__device__ unsigned g_cnt2[BMT/64];   // LN2 tickets

// --------------------------- TF32 helpers ----------------------------------------
__device__ __forceinline__ unsigned f2tf(float x) {
    unsigned u;
    asm("cvt.rna.tf32.f32 %0, %1;" : "=r"(u) : "f"(x));
    return u;
}
__device__ __forceinline__ float tfr(float x) { return __uint_as_float(f2tf(x)); }

__device__ __forceinline__ void mma8(float* d, const unsigned* a, const unsigned* b) {
    asm volatile(
        "mma.sync.aligned.m16n8k8.row.col.f32.tf32.tf32.f32 "
        "{%0,%1,%2,%3}, {%4,%5,%6,%7}, {%8,%9}, {%0,%1,%2,%3};"
        : "+f"(d[0]), "+f"(d[1]), "+f"(d[2]), "+f"(d[3])
        : "r"(a[0]), "r"(a[1]), "r"(a[2]), "r"(a[3]), "r"(b[0]), "r"(b[1]));
}

// ============ TF32 GEMM: 64x64 tile, 3-stage cp.async (tf32-pre-rounded) ==========
// gridDim.z==2 -> split-K: z=1 does upper K half into C2 (no bias/rowadd).
// EK != null: blocks with col0 >= ekcol write bf16 to EK[r*ekld + ekoff + (c-ekcol)].
// lnout != null: last block per row-group computes h = tf32(LN(lnx3+C+C2)*g+b)
// for its 64 rows (ticket pattern; bit-identical to the old k_ln).
__global__ void k_gemmt(const float* __restrict__ A, int lda,
                        const float* __restrict__ Bm, int ldb,
                        float* __restrict__ C, int ldc, int K,
                        const float* __restrict__ bias,
                        const float* __restrict__ rowadd, int ramod, int ldra,
                        int relu, int otf32, float* __restrict__ C2,
                        __nv_bfloat16* __restrict__ EK, int ekcol, int ekoff, int ekld,
                        const float* __restrict__ lnx3, const float* __restrict__ lng,
                        const float* __restrict__ lnbv, float* __restrict__ lnout,
                        unsigned* __restrict__ lncnt)
{
    const int BPAD = 68, ASZ = 64 * 36, BSZ = 32 * BPAD;
    extern __shared__ float sm[];
    float* AsB = sm;            // 3 stages
    float* BsB = sm + 3 * ASZ;

    float* const Cw0 = C;
    float* const Cw1 = C2;

    if (blockIdx.z) { A += K; Bm += (size_t)K * ldb; C = C2; bias = 0; rowadd = 0; }

    const int row0 = blockIdx.y * 64, col0 = blockIdx.x * 64;
    const int tid = threadIdx.x, warp = tid >> 5, lane = tid & 31;
    const int wm = warp >> 2, wn = warp & 3;
    const int l4 = lane >> 2, lm4 = lane & 3;
    const int ar = tid >> 3, akq = (tid & 7) * 4;
    const int brow0 = tid >> 4, bc4 = (tid & 15) * 4;

    float acc[2][2][4] = {};

    auto load = [&](int k0, int s) {
        float* as = AsB + s * ASZ;
        float* bs = BsB + s * BSZ;
#pragma unroll
        for (int i = 0; i < 2; i++) {
            unsigned d = (unsigned)__cvta_generic_to_shared(as + (ar + i * 32) * 36 + akq);
            const float* g = A + (size_t)(row0 + ar + i * 32) * lda + k0 + akq;
            asm volatile("cp.async.cg.shared.global [%0],[%1],16;\n" :: "r"(d), "l"(g));
        }
#pragma unroll
        for (int i = 0; i < 2; i++) {
            int row = brow0 + i * 16;
            unsigned d = (unsigned)__cvta_generic_to_shared(bs + row * BPAD + bc4);
            const float* g = Bm + (size_t)(k0 + row) * ldb + col0 + bc4;
            asm volatile("cp.async.cg.shared.global [%0],[%1],16;\n" :: "r"(d), "l"(g));
        }
        asm volatile("cp.async.commit_group;\n");
    };

    const int nslab = K >> 5;
    load(0, 0);
    if (nslab > 1) load(32, 1); else asm volatile("cp.async.commit_group;\n");

    for (int k = 0; k < nslab; k++) {
        asm volatile("cp.async.wait_group 1;\n");
        __syncthreads();
        if (k + 2 < nslab) load((k + 2) * 32, (k + 2) % 3);
        else               asm volatile("cp.async.commit_group;\n");
        const float* as = AsB + (k % 3) * ASZ;
        const float* bs = BsB + (k % 3) * BSZ;
#pragma unroll
        for (int ks = 0; ks < 4; ks++) {
            const int kk = ks * 8;
            unsigned a[2][4], b[2][2];
#pragma unroll
            for (int mi = 0; mi < 2; mi++) {
                int mb = wm * 32 + mi * 16 + l4;
                a[mi][0] = __float_as_uint(as[mb * 36 + kk + lm4]);
                a[mi][1] = __float_as_uint(as[(mb + 8) * 36 + kk + lm4]);
                a[mi][2] = __float_as_uint(as[mb * 36 + kk + lm4 + 4]);
                a[mi][3] = __float_as_uint(as[(mb + 8) * 36 + kk + lm4 + 4]);
            }
#pragma unroll
            for (int nj = 0; nj < 2; nj++) {
                int nb = wn * 16 + nj * 8 + l4;
                b[nj][0] = __float_as_uint(bs[(kk + lm4) * BPAD + nb]);
                b[nj][1] = __float_as_uint(bs[(kk + lm4 + 4) * BPAD + nb]);
            }
#pragma unroll
            for (int mi = 0; mi < 2; mi++)
#pragma unroll
                for (int nj = 0; nj < 2; nj++)
                    mma8(acc[mi][nj], a[mi], b[nj]);
        }
        __syncthreads();
    }

    const bool ekreg = (EK != 0) && (col0 >= ekcol);
#pragma unroll
    for (int mi = 0; mi < 2; mi++) {
        const int rb = row0 + wm * 32 + mi * 16 + l4;
#pragma unroll
        for (int nj = 0; nj < 2; nj++) {
            const int c = col0 + wn * 16 + nj * 8 + lm4 * 2;
#pragma unroll
            for (int h = 0; h < 2; h++) {
                const int r = rb + h * 8;
                float v0 = acc[mi][nj][h * 2 + 0];
                float v1 = acc[mi][nj][h * 2 + 1];
                if (ekreg) {
                    *(__nv_bfloat162*)(EK + (size_t)r * ekld + ekoff + (c - ekcol)) =
                        __floats2bfloat162_rn(v0, v1);
                    continue;
                }
                if (bias) { v0 += bias[c]; v1 += bias[c + 1]; }
                if (rowadd) {
                    const float* ra = rowadd + (size_t)(r % ramod) * ldra + c;
                    v0 += ra[0]; v1 += ra[1];
                }
                if (relu) { v0 = fmaxf(v0, 0.f); v1 = fmaxf(v1, 0.f); }
                if (otf32) { v0 = tfr(v0); v1 = tfr(v1); }
                *(float2*)(C + (size_t)r * ldc + c) = make_float2(v0, v1);
            }
        }
    }

    // ---- optional LN finalize: last block per row-group does LN for 64 rows ----
    if (lnout) {
        __threadfence();
        __syncthreads();
        __shared__ unsigned s_old;
        if (tid == 0) s_old = atomicAdd(&lncnt[blockIdx.y], 1u);
        __syncthreads();
        const unsigned ntix = gridDim.x * gridDim.z;
        if (s_old == ntix - 1) {
#pragma unroll 1
            for (int rr = 0; rr < 8; rr++) {
                int row = row0 + warp * 8 + rr;
                size_t base = (size_t)row * ldc;
                float v[16];
                float sum = 0.f;
#pragma unroll
                for (int j = 0; j < 16; j++) {
                    int e = lane + j * 32;
                    v[j] = __ldcg(lnx3 + base + e) + __ldcg(Cw0 + base + e)
                         + __ldcg(Cw1 + base + e);
                    sum += v[j];
                }
#pragma unroll
                for (int o = 16; o; o >>= 1) sum += __shfl_xor_sync(0xffffffffu, sum, o);
                float mu = sum * (1.f / 512.f);
                float var = 0.f;
#pragma unroll
                for (int j = 0; j < 16; j++) { float d = v[j] - mu; var += d * d; }
#pragma unroll
                for (int o = 16; o; o >>= 1) var += __shfl_xor_sync(0xffffffffu, var, o);
                float rs = rsqrtf(var * (1.f / 512.f) + 1e-5f);
#pragma unroll
                for (int j = 0; j < 16; j++) {
                    int e = lane + j * 32;
                    lnout[base + e] = tfr((v[j] - mu) * rs * lng[e] + lnbv[e]);
                }
            }
            if (tid == 0) lncnt[blockIdx.y] = 0;   // reset for next step
        }
    }
}

// --------------- legacy converting GEMM core (setup paths only) -------------------
__device__ __forceinline__ void gemm0_body(const float* __restrict__ A, int lda,
                                           const float* __restrict__ Bm, int ldb,
                                           void* __restrict__ Cv, int ldc, int K,
                                           const float* __restrict__ bias, int obf16)
{
    __shared__ __align__(16) unsigned As[128 * 36];
    __shared__ __align__(16) unsigned Bs[32 * 68];
    const int row0 = blockIdx.y * 128, col0 = blockIdx.x * 64;
    const int tid = threadIdx.x;
    const int warp = tid >> 5, lane = tid & 31;
    const int wm = warp >> 1, wn = warp & 1;
    const int l4 = lane >> 2, lm4 = lane & 3;
    const int ar = tid >> 3, akq = (tid & 7) * 4;
    const int br = tid >> 4, bcq = (tid & 15) * 4;

    float acc[2][4][4] = {};
    float4 pa[4], pb[2];
#pragma unroll
    for (int it = 0; it < 4; it++)
        pa[it] = *(const float4*)(A + (size_t)(row0 + ar + it * 32) * lda + akq);
#pragma unroll
    for (int it = 0; it < 2; it++)
        pb[it] = *(const float4*)(Bm + (size_t)(br + it * 16) * ldb + col0 + bcq);

    for (int k0 = 0; k0 < K; k0 += 32) {
#pragma unroll
        for (int it = 0; it < 4; it++) {
            unsigned* p = &As[(ar + it * 32) * 36 + akq];
            p[0] = f2tf(pa[it].x); p[1] = f2tf(pa[it].y);
            p[2] = f2tf(pa[it].z); p[3] = f2tf(pa[it].w);
        }
#pragma unroll
        for (int it = 0; it < 2; it++) {
            unsigned* p = &Bs[(br + it * 16) * 68 + bcq];
            p[0] = f2tf(pb[it].x); p[1] = f2tf(pb[it].y);
            p[2] = f2tf(pb[it].z); p[3] = f2tf(pb[it].w);
        }
        __syncthreads();
        if (k0 + 32 < K) {
#pragma unroll
            for (int it = 0; it < 4; it++)
                pa[it] = *(const float4*)(A + (size_t)(row0 + ar + it * 32) * lda + k0 + 32 + akq);
#pragma unroll
            for (int it = 0; it < 2; it++)
                pb[it] = *(const float4*)(Bm + (size_t)(k0 + 32 + br + it * 16) * ldb + col0 + bcq);
        }
#pragma unroll
        for (int ks = 0; ks < 4; ks++) {
            const int kk = ks * 8;
            unsigned a[2][4], b[4][2];
#pragma unroll
            for (int mi = 0; mi < 2; mi++) {
                int mb = wm * 32 + mi * 16 + l4;
                a[mi][0] = As[mb * 36 + kk + lm4];
                a[mi][1] = As[(mb + 8) * 36 + kk + lm4];
                a[mi][2] = As[mb * 36 + kk + lm4 + 4];
                a[mi][3] = As[(mb + 8) * 36 + kk + lm4 + 4];
            }
#pragma unroll
            for (int nj = 0; nj < 4; nj++) {
                int nb = wn * 32 + nj * 8 + l4;
                b[nj][0] = Bs[(kk + lm4) * 68 + nb];
                b[nj][1] = Bs[(kk + lm4 + 4) * 68 + nb];
            }
#pragma unroll
            for (int mi = 0; mi < 2; mi++)
#pragma unroll
                for (int nj = 0; nj < 4; nj++)
                    mma8(acc[mi][nj], a[mi], b[nj]);
        }
        __syncthreads();
    }
#pragma unroll
    for (int mi = 0; mi < 2; mi++) {
        const int rb = row0 + wm * 32 + mi * 16 + l4;
#pragma unroll
        for (int nj = 0; nj < 4; nj++) {
            const int c = col0 + wn * 32 + nj * 8 + lm4 * 2;
#pragma unroll
            for (int h = 0; h < 2; h++) {
                const int r = rb + h * 8;
                float v0 = acc[mi][nj][h * 2 + 0];
                float v1 = acc[mi][nj][h * 2 + 1];
                if (bias) { v0 += bias[c]; v1 += bias[c + 1]; }
                if (obf16) {
                    *(__nv_bfloat162*)((__nv_bfloat16*)Cv + (size_t)r * ldc + c) =
                        __floats2bfloat162_rn(v0, v1);
                } else {
                    *(float2*)((float*)Cv + (size_t)r * ldc + c) = make_float2(v0, v1);
                }
            }
        }
    }
}

// setup GEMMs, z-dispatch: z=0 cfeat, z=1 cffus, z=2 eKVo
__global__ void k_gemms(const float* __restrict__ feat,
                        const float* __restrict__ Wqkv, const float* __restrict__ bqkv,
                        const float* __restrict__ Wfus, const float* __restrict__ bfus)
{
    if (blockIdx.z == 0) {
        if (blockIdx.x >= 24 || blockIdx.y >= 2) return;
        gemm0_body(feat, 448, Wqkv + 64 * 1536, 1536, g_cfeat, 1536, 448, bqkv, 0);
    } else if (blockIdx.z == 1) {
        if (blockIdx.x >= 7 || blockIdx.y >= 2) return;
        gemm0_body(feat, 448, Wfus + 519 * 448, 448, g_cffus, 448, 448, bfus, 0);
    } else {
        if (blockIdx.x >= 16 || blockIdx.y >= 40) return;
        gemm0_body(g_eobs, 32, Wqkv + 512, 1536, g_eKVo, 1024, 32, (const float*)0, 1);
    }
}

// ---------------- one-time: weights + Wcat + obs embeddings -----------------------
__global__ void k_setup(const float* __restrict__ Wqkv, const float* __restrict__ Wo,
                        const float* __restrict__ Wff1, const float* __restrict__ Wff2,
                        const float* __restrict__ Wfus,
                        const float* __restrict__ obs, const float* __restrict__ Wemb,
                        const float* __restrict__ bemb)
{
    int i = blockIdx.x * 256 + threadIdx.x;
    const int N0 = 64 * 2560, N1 = 512 * 512, N2 = 512 * 2048,
              N3 = 2048 * 512, N4 = 512 * 448, N5 = OBS * NB * 32;
    if (i < N0) {
        int r = i / 2560, c = i - r * 2560;
        float v;
        if (c < 1536)
            v = (r < 32) ? Wqkv[(32 + r) * 1536 + c]
                         : ((c < 512) ? Wqkv[(r - 32) * 1536 + c] : 0.f);
        else
            v = (r < 32) ? 0.f : Wqkv[(r - 32) * 1536 + 512 + (c - 1536)];
        g_Wcat[i] = tfr(v);
        return;
    }
    i -= N0;
    if (i < N1) { g_Wor[i]   = tfr(Wo[i]);   return; } i -= N1;
    if (i < N2) { g_Wff1r[i] = tfr(Wff1[i]); return; } i -= N2;
    if (i < N3) { g_Wff2r[i] = tfr(Wff2[i]); return; } i -= N3;
    if (i < N4) { g_Wfusr[i] = tfr(Wfus[i]); return; } i -= N4;
    if (i < N5) {
        int d = i >> 5, t = i & 31;
        int b = d / OBS, l = d - b * OBS;
        float o0 = obs[(l * NB + b) * 2 + 0];
        float o1 = obs[(l * NB + b) * 2 + 1];
        g_eobs[i] = fmaxf(o0 * Wemb[t] + o1 * Wemb[32 + t] + bemb[t], 0.f);
    }
}

__global__ void k_initprep(const float* __restrict__ obs, const float* __restrict__ Wemb,
                           const float* __restrict__ bemb,
                           const float* __restrict__ loc, const float* __restrict__ feat,
                           const float* __restrict__ Wfus)
{
    int bm = blockIdx.x, tid = threadIdx.x;
    int b = bm & 255, m = bm >> 8;
    float lx = obs[((OBS - 1) * NB + b) * 2 + 0];
    float ly = obs[((OBS - 1) * NB + b) * 2 + 1];
    __shared__ float se[32], ex[32];
    if (tid < 32)
        se[tid] = fmaxf(lx * Wemb[tid] + ly * Wemb[32 + tid] + bemb[tid], 0.f);
    float gx = loc[(b * NM + m) * 2 + 0], gy = loc[(b * NM + m) * 2 + 1];
    float dx = gx - lx, dy = gy - ly;
    float t = (float)OBS;
    __syncthreads();
    if (tid < 32) {
        float v;
        if (tid < 8)       v = (tid & 1) ? gy : gx;
        else if (tid < 16) v = (tid & 1) ? ly : lx;
        else if (tid < 24) v = (tid & 1) ? dy : dx;
        else               v = t;
        ex[tid] = v;
        g_E[bm * 64 + tid] = tfr(v);
        g_E[bm * 64 + 32 + tid] = tfr(se[tid]);
    }
    __syncthreads();
    for (int c = tid; c < 512; c += 128) {
        float v;
        if (c < 32)      v = se[c];
        else if (c < 64) v = ex[c - 32];
        else             v = feat[b * INC + (c - 64)];
        g_xlast[bm * 512 + c] = v;
    }
    for (int c = tid; c < 448; c += 128) {
        float v = g_cffus[b * 448 + c];
        v += lx * Wfus[(512 + 0) * 448 + c];
        v += ly * Wfus[(512 + 1) * 448 + c];
        v += gx * Wfus[(512 + 2) * 448 + c];
        v += gy * Wfus[(512 + 3) * 448 + c];
        v += dx * Wfus[(512 + 4) * 448 + c];
        v += dy * Wfus[(512 + 5) * 448 + c];
        v += t  * Wfus[(512 + 6) * 448 + c];
        g_rowfus[bm * 448 + c] = v;
    }
}

// ------------------------- per-step attention (bm0 = group row base) ---------------
__global__ void k_attn(int f, int bm0)
{
    int bm = blockIdx.x + bm0;
    int tid = threadIdx.x, w = tid >> 5, lane = tid & 31;
    int b = bm & 255;
    const float* qp = g_QKVC + (size_t)bm * 1536 + w * 64;
    float q0 = qp[2 * lane], q1 = qp[2 * lane + 1];
    const float* ckp = qp + 512;
    float s = q0 * ckp[2 * lane] + q1 * ckp[2 * lane + 1];
#pragma unroll
    for (int o = 16; o; o >>= 1) s += __shfl_xor_sync(0xffffffffu, s, o);
    const float qdot = s;
    __shared__ float sp[8][56];
    const int off = w * 64 + 2 * lane;
    const __nv_bfloat16* ob = g_eKVo + (size_t)b * OBS * 1024 + off;
    const __nv_bfloat16* rbp = g_eKV + (size_t)bm * HOR * 1024 + off;
    const int fr = f - OBS;
    for (int l = 0; l < OBS; l++) {
        float2 kf = __bfloat1622float2(*(const __nv_bfloat162*)(ob + l * 1024));
        float d = q0 * kf.x + q1 * kf.y;
#pragma unroll
        for (int o = 16; o; o >>= 1) d += __shfl_xor_sync(0xffffffffu, d, o);
        if (lane == 0) sp[w][l] = (d + qdot) * 0.125f;
    }
    for (int l = 0; l < fr; l++) {
        float2 kf = __bfloat1622float2(*(const __nv_bfloat162*)(rbp + l * 1024));
        float d = q0 * kf.x + q1 * kf.y;
#pragma unroll
        for (int o = 16; o; o >>= 1) d += __shfl_xor_sync(0xffffffffu, d, o);
        if (lane == 0) sp[w][OBS + l] = (d + qdot) * 0.125f;
    }
    __syncwarp();
    float mx = -1e30f;
    if (lane < f)      mx = sp[w][lane];
    if (lane + 32 < f) mx = fmaxf(mx, sp[w][lane + 32]);
#pragma unroll
    for (int o = 16; o; o >>= 1) mx = fmaxf(mx, __shfl_xor_sync(0xffffffffu, mx, o));
    float e0 = 0.f, e1 = 0.f;
    if (lane < f)      e0 = expf(sp[w][lane] - mx);
    if (lane + 32 < f) e1 = expf(sp[w][lane + 32] - mx);
    float sum = e0 + e1;
#pragma unroll
    for (int o = 16; o; o >>= 1) sum += __shfl_xor_sync(0xffffffffu, sum, o);
    if (lane < f)      sp[w][lane] = e0;
    if (lane + 32 < f) sp[w][lane + 32] = e1;
    __syncwarp();
    float inv = 1.f / sum;
    const float* cvp = qp + 1024;
    float a0 = 0.f, a1 = 0.f;
    for (int l = 0; l < OBS; l++) {
        float p = sp[w][l];
        float2 vf = __bfloat1622float2(*(const __nv_bfloat162*)(ob + 512 + l * 1024));
        a0 += p * vf.x; a1 += p * vf.y;
    }
    for (int l = 0; l < fr; l++) {
        float p = sp[w][OBS + l];
        float2 vf = __bfloat1622float2(*(const __nv_bfloat162*)(rbp + 512 + l * 1024));
        a0 += p * vf.x; a1 += p * vf.y;
    }
    float* op = g_ctx + (size_t)bm * 512 + off;
    *(float2*)op = make_float2(tfr(cvp[2 * lane] + a0 * inv),
                               tfr(cvp[2 * lane + 1] + a1 * inv));
}

// ---- fused per-step epilogue: out + emb + prep for step f+1 ---------------------
__global__ void k_step(const float* __restrict__ Wout, const float* __restrict__ bout,
                       const float* __restrict__ Wemb, const float* __restrict__ bemb,
                       const float* __restrict__ loc, const float* __restrict__ feat,
                       const float* __restrict__ Wfus,
                       float* __restrict__ dout, int f, int bm0)
{
    int bm = blockIdx.x + bm0, tid = threadIdx.x;
    int w = tid >> 5, lane = tid & 31;
    int b = bm & 255, m = bm >> 8;
    __shared__ float r0[4], r1[4];
    __shared__ float se[32], ex[32];

    float s0 = 0.f, s1 = 0.f;
    const float* fp  = g_fus  + (size_t)bm * 448;
    const float* fpb = g_fusb + (size_t)bm * 448;
    for (int c = tid; c < 448; c += 128) {
        float v = fp[c] + fpb[c];
        s0 += v * Wout[c * 2 + 0];
        s1 += v * Wout[c * 2 + 1];
    }
#pragma unroll
    for (int o = 16; o; o >>= 1) {
        s0 += __shfl_xor_sync(0xffffffffu, s0, o);
        s1 += __shfl_xor_sync(0xffffffffu, s1, o);
    }
    if (lane == 0) { r0[w] = s0; r1[w] = s1; }
    __syncthreads();
    float o0 = r0[0] + r0[1] + r0[2] + r0[3] + bout[0];
    float o1 = r1[0] + r1[1] + r1[2] + r1[3] + bout[1];

    if (tid < 32)
        se[tid] = fmaxf(o0 * Wemb[tid] + o1 * Wemb[32 + tid] + bemb[tid], 0.f);
    if (tid == 0) {
        int t = f - OBS;
        dout[b * (NM * HOR * 2) + m * (HOR * 2) + t * 2 + 0] = o0;
        dout[b * (NM * HOR * 2) + m * (HOR * 2) + t * 2 + 1] = o1;
    }
    __syncthreads();

    int fn = f + 1;
    if (fn < OBS + HOR) {
        float gx = loc[(b * NM + m) * 2 + 0], gy = loc[(b * NM + m) * 2 + 1];
        float dx = gx - o0, dy = gy - o1;
        float t = (float)fn;
        if (tid < 32) {
            float v;
            if (tid < 8)       v = (tid & 1) ? gy : gx;
            else if (tid < 16) v = (tid & 1) ? o1 : o0;
            else if (tid < 24) v = (tid & 1) ? dy : dx;
            else               v = t;
            ex[tid] = v;
            g_E[bm * 64 + tid] = tfr(v);
            g_E[bm * 64 + 32 + tid] = tfr(se[tid]);
        }
        __syncthreads();
        for (int c = tid; c < 512; c += 128) {
            float v;
            if (c < 32)      v = se[c];
            else if (c < 64) v = ex[c - 32];
            else             v = feat[b * INC + (c - 64)];
            g_xlast[bm * 512 + c] = v;
        }
        for (int c = tid; c < 448; c += 128) {
            float v = g_cffus[b * 448 + c];
            v += o0 * Wfus[(512 + 0) * 448 + c];
            v += o1 * Wfus[(512 + 1) * 448 + c];
            v += gx * Wfus[(512 + 2) * 448 + c];
            v += gy * Wfus[(512 + 3) * 448 + c];
            v += dx * Wfus[(512 + 4) * 448 + c];
            v += dy * Wfus[(512 + 5) * 448 + c];
            v += t  * Wfus[(512 + 6) * 448 + c];
            g_rowfus[bm * 448 + c] = v;
        }
    }
}

// ----------------------------------- launch ---------------------------------------
extern "C" void kernel_launch(void* const* d_in, const int* in_sizes, int n_in,
                              void* d_out, int out_size)
{
    const float* feat = (const float*)d_in[0];
    const float* loc  = (const float*)d_in[1];
    const float* obs  = (const float*)d_in[2];
    const float* Wemb = (const float*)d_in[3];
    const float* bemb = (const float*)d_in[4];
    const float* Wqkv = (const float*)d_in[5];
    const float* bqkv = (const float*)d_in[6];
    const float* Wo   = (const float*)d_in[7];
    const float* bo   = (const float*)d_in[8];
    const float* Wff1 = (const float*)d_in[9];
    const float* bff1 = (const float*)d_in[10];
    const float* Wff2 = (const float*)d_in[11];
    const float* bff2 = (const float*)d_in[12];
    const float* ln1g = (const float*)d_in[13];
    const float* ln1b = (const float*)d_in[14];
    const float* ln2g = (const float*)d_in[15];
    const float* ln2b = (const float*)d_in[16];
    const float* Wfus = (const float*)d_in[17];
    const float* bfus = (const float*)d_in[18];
    const float* Wout = (const float*)d_in[19];
    const float* bout = (const float*)d_in[20];
    float* outp = (float*)d_out;

    float *cfeat, *E, *xlast, *rowfus, *QKVC, *ctx, *wo, *wob, *h1, *ff1, *ff2,
          *ff2b, *h2, *fus, *fusb, *Wor, *Wff1r, *Wff2r, *Wfusr, *Wcat;
    unsigned *cnt1, *cnt2;
    __nv_bfloat16 *eKV;
    cudaGetSymbolAddress((void**)&cfeat,  g_cfeat);
    cudaGetSymbolAddress((void**)&Wcat,   g_Wcat);
    cudaGetSymbolAddress((void**)&Wor,    g_Wor);
    cudaGetSymbolAddress((void**)&Wff1r,  g_Wff1r);
    cudaGetSymbolAddress((void**)&Wff2r,  g_Wff2r);
    cudaGetSymbolAddress((void**)&Wfusr,  g_Wfusr);
    cudaGetSymbolAddress((void**)&eKV,    g_eKV);
    cudaGetSymbolAddress((void**)&E,      g_E);
    cudaGetSymbolAddress((void**)&xlast,  g_xlast);
    cudaGetSymbolAddress((void**)&rowfus, g_rowfus);
    cudaGetSymbolAddress((void**)&QKVC,   g_QKVC);
    cudaGetSymbolAddress((void**)&ctx,    g_ctx);
    cudaGetSymbolAddress((void**)&wo,     g_wo);
    cudaGetSymbolAddress((void**)&wob,    g_wob);
    cudaGetSymbolAddress((void**)&h1,     g_h1);
    cudaGetSymbolAddress((void**)&ff1,    g_ff1);
    cudaGetSymbolAddress((void**)&ff2,    g_ff2);
    cudaGetSymbolAddress((void**)&ff2b,   g_ff2b);
    cudaGetSymbolAddress((void**)&h2,     g_h2);
    cudaGetSymbolAddress((void**)&fus,    g_fus);
    cudaGetSymbolAddress((void**)&fusb,   g_fusb);
    cudaGetSymbolAddress((void**)&cnt1,   g_cnt1);
    cudaGetSymbolAddress((void**)&cnt2,   g_cnt2);

    const float* NUL = (const float*)0;
    float* FNUL = (float*)0;
    __nv_bfloat16* BNUL = (__nv_bfloat16*)0;
    unsigned* UNUL = (unsigned*)0;

    const int SMEMT = 3 * (64 * 36 + 32 * 68) * 4;  // 53760
    cudaFuncSetAttribute(k_gemmt, cudaFuncAttributeMaxDynamicSharedMemorySize, SMEMT);

    static cudaStream_t gs[NGRP - 1];
    static cudaEvent_t  evFork, evJoin[NGRP - 1];
    static int s_init = 0;
    if (!s_init) {
        for (int i = 0; i < NGRP - 1; i++)
            cudaStreamCreateWithFlags(&gs[i], cudaStreamNonBlocking);
        cudaEventCreateWithFlags(&evFork, cudaEventDisableTiming);
        for (int i = 0; i < NGRP - 1; i++)
            cudaEventCreateWithFlags(&evJoin[i], cudaEventDisableTiming);
        s_init = 1;
    }

    // ---- setup (main stream) ----
    const int NSET = 64 * 2560 + 512 * 512 + 512 * 2048 + 2048 * 512 + 512 * 448
                   + OBS * NB * 32;
    k_setup<<<(NSET + 255) / 256, 256>>>(Wqkv, Wo, Wff1, Wff2, Wfus, obs, Wemb, bemb);
    k_gemms<<<dim3(24, 40, 3), 256>>>(feat, Wqkv, bqkv, Wfus, bfus);
    k_initprep<<<BMT, 128>>>(obs, Wemb, bemb, loc, feat, Wfus);

    cudaEventRecord(evFork, 0);
    for (int i = 0; i < NGRP - 1; i++) cudaStreamWaitEvent(gs[i], evFork, 0);

    const int EKLD = HOR * 1024;
    const int GY = GROWS / 64;   // 8
    for (int g = 0; g < NGRP; g++) {
        cudaStream_t st = (g == 0) ? (cudaStream_t)0 : gs[g - 1];
        const int off = g * GROWS;
        float* Eg   = E + (size_t)off * 64;
        float* Qg   = QKVC + (size_t)off * 1536;
        float* ctxg = ctx + (size_t)off * 512;
        float* wog  = wo + (size_t)off * 512;
        float* wobg = wob + (size_t)off * 512;
        float* xlg  = xlast + (size_t)off * 512;
        float* h1g  = h1 + (size_t)off * 512;
        float* ff1g = ff1 + (size_t)off * 2048;
        float* ff2g = ff2 + (size_t)off * 512;
        float* f2bg = ff2b + (size_t)off * 512;
        float* h2g  = h2 + (size_t)off * 512;
        float* fusg = fus + (size_t)off * 448;
        float* fubg = fusb + (size_t)off * 448;
        float* rfg  = rowfus + (size_t)off * 448;
        __nv_bfloat16* eKVg = eKV + (size_t)off * EKLD;
        unsigned* c1g = cnt1 + g * GY;
        unsigned* c2g = cnt2 + g * GY;

        for (int f = OBS; f < OBS + HOR; f++) {
            int ekoff = ((f == OBS) ? (HOR - 1) : (f - 1 - OBS)) * 1024;
            // 1. QKVC + eKV (K=64)
            k_gemmt<<<dim3(40, GY), 256, SMEMT, st>>>(Eg, 64, Wcat, 2560, Qg, 1536, 64,
                                                      NUL, cfeat, 256, 1536, 0, 0, FNUL,
                                                      eKVg, 1536, ekoff, EKLD,
                                                      NUL, NUL, NUL, FNUL, UNUL);
            // 2. attention
            k_attn<<<GROWS, 256, 0, st>>>(f, off);
            // 3. wo(+wob) = ctx @ W_o + b_o; last block per 64-row group does LN1 -> h1
            k_gemmt<<<dim3(8, GY, 2), 256, SMEMT, st>>>(ctxg, 512, Wor, 512, wog, 512, 256,
                                                        bo, NUL, 1, 0, 0, 0, wobg,
                                                        BNUL, 1 << 30, 0, 0,
                                                        xlg, ln1g, ln1b, h1g, c1g);
            // 4. ff1 = tf32(relu(h1 @ Wff1 + b))
            k_gemmt<<<dim3(32, GY), 256, SMEMT, st>>>(h1g, 512, Wff1r, 2048, ff1g, 2048, 512,
                                                      bff1, NUL, 1, 0, 1, 1, FNUL,
                                                      BNUL, 1 << 30, 0, 0,
                                                      NUL, NUL, NUL, FNUL, UNUL);
            // 5. ff2(+ff2b) = ff1 @ Wff2 + b; last block per group does LN2 -> h2
            k_gemmt<<<dim3(8, GY, 2), 256, SMEMT, st>>>(ff1g, 2048, Wff2r, 512, ff2g, 512, 1024,
                                                        bff2, NUL, 1, 0, 0, 0, f2bg,
                                                        BNUL, 1 << 30, 0, 0,
                                                        h1g, ln2g, ln2b, h2g, c2g);
            // 6. fus(+fusb) = h2 @ Wfus + rowfus  (split-K 256+256)
            k_gemmt<<<dim3(7, GY, 2), 256, SMEMT, st>>>(h2g, 512, Wfusr, 448, fusg, 448, 256,
                                                        NUL, rfg, GROWS, 448, 0, 0, fubg,
                                                        BNUL, 1 << 30, 0, 0,
                                                        NUL, NUL, NUL, FNUL, UNUL);
            // 7. out + emb + prep(f+1)
            k_step<<<GROWS, 128, 0, st>>>(Wout, bout, Wemb, bemb, loc, feat, Wfus,
                                          outp, f, off);
        }
    }

    for (int i = 0; i < NGRP - 1; i++) {
        cudaEventRecord(evJoin[i], gs[i]);
        cudaStreamWaitEvent((cudaStream_t)0, evJoin[i], 0);
    }
    (void)in_sizes; (void)n_in; (void)out_size;
}

// round 17
// speedup vs baseline: 1.4524x; 1.1333x over previous
#include <cuda_runtime.h>
#include <cuda_bf16.h>
#include <math.h>

#define NB    256
#define NM    6
#define INC   448
#define EMB   32
#define OBS   20
#define HOR   30
#define DD    512
#define DFF   2048
#define BMT   1536     // NB*NM
#define NGRP  3        // independent goal-groups (2 goals each), one stream per group
#define GROWS (BMT / NGRP)   // 512 rows per group

// ------------------------- scratch (static device globals) -------------------------
__device__ __align__(256) float g_cfeat[NB*1536];
__device__ __align__(256) float g_cffus[NB*448];
__device__ __align__(256) float g_Wcat[64*2560];       // tf32; cols 1536:2560 = emb->eKV map
__device__ __align__(256) float g_Wor[512*512];
__device__ __align__(256) float g_Wff1r[512*2048];
__device__ __align__(256) float g_Wff2r[2048*512];
__device__ __align__(256) float g_Wfusr[512*448];
__device__ __align__(256) float g_eobs[OBS*NB*32];     // rows ordered [b][l]
__device__ __align__(256) __nv_bfloat16 g_eKVo[(size_t)NB*OBS*1024];   // [b][l][1024]
__device__ __align__(256) __nv_bfloat16 g_eKV[(size_t)BMT*HOR*1024];   // [bm][slot][1024]
__device__ __align__(256) float g_E[BMT*64];
__device__ __align__(256) float g_xlast[BMT*DD];
__device__ __align__(256) float g_rowfus[BMT*448];
__device__ __align__(256) float g_QKVC[BMT*1536];
__device__ __align__(256) float g_ctx[BMT*DD];
__device__ __align__(256) float g_wo[BMT*DD];
__device__ __align__(256) float g_wob[BMT*DD];
__device__ __align__(256) float g_h1[BMT*DD];
__device__ __align__(256) float g_ff1[BMT*DFF];
__device__ __align__(256) float g_ff2[BMT*DD];
__device__ __align__(256) float g_ff2b[BMT*DD];
__device__ __align__(256) float g_h2[BMT*DD];
__device__ __align__(256) float g_fus[BMT*448];
__device__ __align__(256) float g_fusb[BMT*448];

// --------------------------- TF32 helpers ----------------------------------------
__device__ __forceinline__ unsigned f2tf(float x) {
    unsigned u;
    asm("cvt.rna.tf32.f32 %0, %1;" : "=r"(u) : "f"(x));
    return u;
}
__device__ __forceinline__ float tfr(float x) { return __uint_as_float(f2tf(x)); }

__device__ __forceinline__ void mma8(float* d, const unsigned* a, const unsigned* b) {
    asm volatile(
        "mma.sync.aligned.m16n8k8.row.col.f32.tf32.tf32.f32 "
        "{%0,%1,%2,%3}, {%4,%5,%6,%7}, {%8,%9}, {%0,%1,%2,%3};"
        : "+f"(d[0]), "+f"(d[1]), "+f"(d[2]), "+f"(d[3])
        : "r"(a[0]), "r"(a[1]), "r"(a[2]), "r"(a[3]), "r"(b[0]), "r"(b[1]));
}

// ============ TF32 GEMM: 64x64 tile, 3-stage cp.async (tf32-pre-rounded) ==========
// gridDim.z==2 -> split-K: z=1 does upper K half into C2 (no bias/rowadd).
// EK != null: blocks with col0 >= ekcol write bf16 to EK[r*ekld + ekoff + (c-ekcol)].
__global__ void k_gemmt(const float* __restrict__ A, int lda,
                        const float* __restrict__ Bm, int ldb,
                        float* __restrict__ C, int ldc, int K,
                        const float* __restrict__ bias,
                        const float* __restrict__ rowadd, int ramod, int ldra,
                        int relu, int otf32, float* __restrict__ C2,
                        __nv_bfloat16* __restrict__ EK, int ekcol, int ekoff, int ekld)
{
    const int BPAD = 68, ASZ = 64 * 36, BSZ = 32 * BPAD;
    extern __shared__ float sm[];
    float* AsB = sm;            // 3 stages
    float* BsB = sm + 3 * ASZ;

    if (blockIdx.z) { A += K; Bm += (size_t)K * ldb; C = C2; bias = 0; rowadd = 0; }

    const int row0 = blockIdx.y * 64, col0 = blockIdx.x * 64;
    const int tid = threadIdx.x, warp = tid >> 5, lane = tid & 31;
    const int wm = warp >> 2, wn = warp & 3;
    const int l4 = lane >> 2, lm4 = lane & 3;
    const int ar = tid >> 3, akq = (tid & 7) * 4;
    const int brow0 = tid >> 4, bc4 = (tid & 15) * 4;

    float acc[2][2][4] = {};

    auto load = [&](int k0, int s) {
        float* as = AsB + s * ASZ;
        float* bs = BsB + s * BSZ;
#pragma unroll
        for (int i = 0; i < 2; i++) {
            unsigned d = (unsigned)__cvta_generic_to_shared(as + (ar + i * 32) * 36 + akq);
            const float* g = A + (size_t)(row0 + ar + i * 32) * lda + k0 + akq;
            asm volatile("cp.async.cg.shared.global [%0],[%1],16;\n" :: "r"(d), "l"(g));
        }
#pragma unroll
        for (int i = 0; i < 2; i++) {
            int row = brow0 + i * 16;
            unsigned d = (unsigned)__cvta_generic_to_shared(bs + row * BPAD + bc4);
            const float* g = Bm + (size_t)(k0 + row) * ldb + col0 + bc4;
            asm volatile("cp.async.cg.shared.global [%0],[%1],16;\n" :: "r"(d), "l"(g));
        }
        asm volatile("cp.async.commit_group;\n");
    };

    const int nslab = K >> 5;
    load(0, 0);
    if (nslab > 1) load(32, 1); else asm volatile("cp.async.commit_group;\n");

    for (int k = 0; k < nslab; k++) {
        asm volatile("cp.async.wait_group 1;\n");
        __syncthreads();
        if (k + 2 < nslab) load((k + 2) * 32, (k + 2) % 3);
        else               asm volatile("cp.async.commit_group;\n");
        const float* as = AsB + (k % 3) * ASZ;
        const float* bs = BsB + (k % 3) * BSZ;
#pragma unroll
        for (int ks = 0; ks < 4; ks++) {
            const int kk = ks * 8;
            unsigned a[2][4], b[2][2];
#pragma unroll
            for (int mi = 0; mi < 2; mi++) {
                int mb = wm * 32 + mi * 16 + l4;
                a[mi][0] = __float_as_uint(as[mb * 36 + kk + lm4]);
                a[mi][1] = __float_as_uint(as[(mb + 8) * 36 + kk + lm4]);
                a[mi][2] = __float_as_uint(as[mb * 36 + kk + lm4 + 4]);
                a[mi][3] = __float_as_uint(as[(mb + 8) * 36 + kk + lm4 + 4]);
            }
#pragma unroll
            for (int nj = 0; nj < 2; nj++) {
                int nb = wn * 16 + nj * 8 + l4;
                b[nj][0] = __float_as_uint(bs[(kk + lm4) * BPAD + nb]);
                b[nj][1] = __float_as_uint(bs[(kk + lm4 + 4) * BPAD + nb]);
            }
#pragma unroll
            for (int mi = 0; mi < 2; mi++)
#pragma unroll
                for (int nj = 0; nj < 2; nj++)
                    mma8(acc[mi][nj], a[mi], b[nj]);
        }
        __syncthreads();
    }

    const bool ekreg = (EK != 0) && (col0 >= ekcol);
#pragma unroll
    for (int mi = 0; mi < 2; mi++) {
        const int rb = row0 + wm * 32 + mi * 16 + l4;
#pragma unroll
        for (int nj = 0; nj < 2; nj++) {
            const int c = col0 + wn * 16 + nj * 8 + lm4 * 2;
#pragma unroll
            for (int h = 0; h < 2; h++) {
                const int r = rb + h * 8;
                float v0 = acc[mi][nj][h * 2 + 0];
                float v1 = acc[mi][nj][h * 2 + 1];
                if (ekreg) {
                    *(__nv_bfloat162*)(EK + (size_t)r * ekld + ekoff + (c - ekcol)) =
                        __floats2bfloat162_rn(v0, v1);
                    continue;
                }
                if (bias) { v0 += bias[c]; v1 += bias[c + 1]; }
                if (rowadd) {
                    const float* ra = rowadd + (size_t)(r % ramod) * ldra + c;
                    v0 += ra[0]; v1 += ra[1];
                }
                if (relu) { v0 = fmaxf(v0, 0.f); v1 = fmaxf(v1, 0.f); }
                if (otf32) { v0 = tfr(v0); v1 = tfr(v1); }
                *(float2*)(C + (size_t)r * ldc + c) = make_float2(v0, v1);
            }
        }
    }
}

// --------------- legacy converting GEMM core (setup paths only) -------------------
__device__ __forceinline__ void gemm0_body(const float* __restrict__ A, int lda,
                                           const float* __restrict__ Bm, int ldb,
                                           void* __restrict__ Cv, int ldc, int K,
                                           const float* __restrict__ bias, int obf16)
{
    __shared__ __align__(16) unsigned As[128 * 36];
    __shared__ __align__(16) unsigned Bs[32 * 68];
    const int row0 = blockIdx.y * 128, col0 = blockIdx.x * 64;
    const int tid = threadIdx.x;
    const int warp = tid >> 5, lane = tid & 31;
    const int wm = warp >> 1, wn = warp & 1;
    const int l4 = lane >> 2, lm4 = lane & 3;
    const int ar = tid >> 3, akq = (tid & 7) * 4;
    const int br = tid >> 4, bcq = (tid & 15) * 4;

    float acc[2][4][4] = {};
    float4 pa[4], pb[2];
#pragma unroll
    for (int it = 0; it < 4; it++)
        pa[it] = *(const float4*)(A + (size_t)(row0 + ar + it * 32) * lda + akq);
#pragma unroll
    for (int it = 0; it < 2; it++)
        pb[it] = *(const float4*)(Bm + (size_t)(br + it * 16) * ldb + col0 + bcq);

    for (int k0 = 0; k0 < K; k0 += 32) {
#pragma unroll
        for (int it = 0; it < 4; it++) {
            unsigned* p = &As[(ar + it * 32) * 36 + akq];
            p[0] = f2tf(pa[it].x); p[1] = f2tf(pa[it].y);
            p[2] = f2tf(pa[it].z); p[3] = f2tf(pa[it].w);
        }
#pragma unroll
        for (int it = 0; it < 2; it++) {
            unsigned* p = &Bs[(br + it * 16) * 68 + bcq];
            p[0] = f2tf(pb[it].x); p[1] = f2tf(pb[it].y);
            p[2] = f2tf(pb[it].z); p[3] = f2tf(pb[it].w);
        }
        __syncthreads();
        if (k0 + 32 < K) {
#pragma unroll
            for (int it = 0; it < 4; it++)
                pa[it] = *(const float4*)(A + (size_t)(row0 + ar + it * 32) * lda + k0 + 32 + akq);
#pragma unroll
            for (int it = 0; it < 2; it++)
                pb[it] = *(const float4*)(Bm + (size_t)(k0 + 32 + br + it * 16) * ldb + col0 + bcq);
        }
#pragma unroll
        for (int ks = 0; ks < 4; ks++) {
            const int kk = ks * 8;
            unsigned a[2][4], b[4][2];
#pragma unroll
            for (int mi = 0; mi < 2; mi++) {
                int mb = wm * 32 + mi * 16 + l4;
                a[mi][0] = As[mb * 36 + kk + lm4];
                a[mi][1] = As[(mb + 8) * 36 + kk + lm4];
                a[mi][2] = As[mb * 36 + kk + lm4 + 4];
                a[mi][3] = As[(mb + 8) * 36 + kk + lm4 + 4];
            }
#pragma unroll
            for (int nj = 0; nj < 4; nj++) {
                int nb = wn * 32 + nj * 8 + l4;
                b[nj][0] = Bs[(kk + lm4) * 68 + nb];
                b[nj][1] = Bs[(kk + lm4 + 4) * 68 + nb];
            }
#pragma unroll
            for (int mi = 0; mi < 2; mi++)
#pragma unroll
                for (int nj = 0; nj < 4; nj++)
                    mma8(acc[mi][nj], a[mi], b[nj]);
        }
        __syncthreads();
    }
#pragma unroll
    for (int mi = 0; mi < 2; mi++) {
        const int rb = row0 + wm * 32 + mi * 16 + l4;
#pragma unroll
        for (int nj = 0; nj < 4; nj++) {
            const int c = col0 + wn * 32 + nj * 8 + lm4 * 2;
#pragma unroll
            for (int h = 0; h < 2; h++) {
                const int r = rb + h * 8;
                float v0 = acc[mi][nj][h * 2 + 0];
                float v1 = acc[mi][nj][h * 2 + 1];
                if (bias) { v0 += bias[c]; v1 += bias[c + 1]; }
                if (obf16) {
                    *(__nv_bfloat162*)((__nv_bfloat16*)Cv + (size_t)r * ldc + c) =
                        __floats2bfloat162_rn(v0, v1);
                } else {
                    *(float2*)((float*)Cv + (size_t)r * ldc + c) = make_float2(v0, v1);
                }
            }
        }
    }
}

// setup GEMMs, z-dispatch: z=0 cfeat, z=1 cffus, z=2 eKVo
__global__ void k_gemms(const float* __restrict__ feat,
                        const float* __restrict__ Wqkv, const float* __restrict__ bqkv,
                        const float* __restrict__ Wfus, const float* __restrict__ bfus)
{
    if (blockIdx.z == 0) {
        if (blockIdx.x >= 24 || blockIdx.y >= 2) return;
        gemm0_body(feat, 448, Wqkv + 64 * 1536, 1536, g_cfeat, 1536, 448, bqkv, 0);
    } else if (blockIdx.z == 1) {
        if (blockIdx.x >= 7 || blockIdx.y >= 2) return;
        gemm0_body(feat, 448, Wfus + 519 * 448, 448, g_cffus, 448, 448, bfus, 0);
    } else {
        if (blockIdx.x >= 16 || blockIdx.y >= 40) return;
        gemm0_body(g_eobs, 32, Wqkv + 512, 1536, g_eKVo, 1024, 32, (const float*)0, 1);
    }
}

// ---------------- one-time: weights + Wcat + obs embeddings -----------------------
__global__ void k_setup(const float* __restrict__ Wqkv, const float* __restrict__ Wo,
                        const float* __restrict__ Wff1, const float* __restrict__ Wff2,
                        const float* __restrict__ Wfus,
                        const float* __restrict__ obs, const float* __restrict__ Wemb,
                        const float* __restrict__ bemb)
{
    int i = blockIdx.x * 256 + threadIdx.x;
    const int N0 = 64 * 2560, N1 = 512 * 512, N2 = 512 * 2048,
              N3 = 2048 * 512, N4 = 512 * 448, N5 = OBS * NB * 32;
    if (i < N0) {
        int r = i / 2560, c = i - r * 2560;
        float v;
        if (c < 1536)
            v = (r < 32) ? Wqkv[(32 + r) * 1536 + c]
                         : ((c < 512) ? Wqkv[(r - 32) * 1536 + c] : 0.f);
        else
            v = (r < 32) ? 0.f : Wqkv[(r - 32) * 1536 + 512 + (c - 1536)];
        g_Wcat[i] = tfr(v);
        return;
    }
    i -= N0;
    if (i < N1) { g_Wor[i]   = tfr(Wo[i]);   return; } i -= N1;
    if (i < N2) { g_Wff1r[i] = tfr(Wff1[i]); return; } i -= N2;
    if (i < N3) { g_Wff2r[i] = tfr(Wff2[i]); return; } i -= N3;
    if (i < N4) { g_Wfusr[i] = tfr(Wfus[i]); return; } i -= N4;
    if (i < N5) {
        int d = i >> 5, t = i & 31;
        int b = d / OBS, l = d - b * OBS;
        float o0 = obs[(l * NB + b) * 2 + 0];
        float o1 = obs[(l * NB + b) * 2 + 1];
        g_eobs[i] = fmaxf(o0 * Wemb[t] + o1 * Wemb[32 + t] + bemb[t], 0.f);
    }
}

__global__ void k_initprep(const float* __restrict__ obs, const float* __restrict__ Wemb,
                           const float* __restrict__ bemb,
                           const float* __restrict__ loc, const float* __restrict__ feat,
                           const float* __restrict__ Wfus)
{
    int bm = blockIdx.x, tid = threadIdx.x;
    int b = bm & 255, m = bm >> 8;
    float lx = obs[((OBS - 1) * NB + b) * 2 + 0];
    float ly = obs[((OBS - 1) * NB + b) * 2 + 1];
    __shared__ float se[32], ex[32];
    if (tid < 32)
        se[tid] = fmaxf(lx * Wemb[tid] + ly * Wemb[32 + tid] + bemb[tid], 0.f);
    float gx = loc[(b * NM + m) * 2 + 0], gy = loc[(b * NM + m) * 2 + 1];
    float dx = gx - lx, dy = gy - ly;
    float t = (float)OBS;
    __syncthreads();
    if (tid < 32) {
        float v;
        if (tid < 8)       v = (tid & 1) ? gy : gx;
        else if (tid < 16) v = (tid & 1) ? ly : lx;
        else if (tid < 24) v = (tid & 1) ? dy : dx;
        else               v = t;
        ex[tid] = v;
        g_E[bm * 64 + tid] = tfr(v);
        g_E[bm * 64 + 32 + tid] = tfr(se[tid]);
    }
    __syncthreads();
    for (int c = tid; c < 512; c += 128) {
        float v;
        if (c < 32)      v = se[c];
        else if (c < 64) v = ex[c - 32];
        else             v = feat[b * INC + (c - 64)];
        g_xlast[bm * 512 + c] = v;
    }
    for (int c = tid; c < 448; c += 128) {
        float v = g_cffus[b * 448 + c];
        v += lx * Wfus[(512 + 0) * 448 + c];
        v += ly * Wfus[(512 + 1) * 448 + c];
        v += gx * Wfus[(512 + 2) * 448 + c];
        v += gy * Wfus[(512 + 3) * 448 + c];
        v += dx * Wfus[(512 + 4) * 448 + c];
        v += dy * Wfus[(512 + 5) * 448 + c];
        v += t  * Wfus[(512 + 6) * 448 + c];
        g_rowfus[bm * 448 + c] = v;
    }
}

// ------------------------- per-step attention (bm0 = group row base) ---------------
__global__ void k_attn(int f, int bm0)
{
    int bm = blockIdx.x + bm0;
    int tid = threadIdx.x, w = tid >> 5, lane = tid & 31;
    int b = bm & 255;
    const float* qp = g_QKVC + (size_t)bm * 1536 + w * 64;
    float q0 = qp[2 * lane], q1 = qp[2 * lane + 1];
    const float* ckp = qp + 512;
    float s = q0 * ckp[2 * lane] + q1 * ckp[2 * lane + 1];
#pragma unroll
    for (int o = 16; o; o >>= 1) s += __shfl_xor_sync(0xffffffffu, s, o);
    const float qdot = s;
    __shared__ float sp[8][56];
    const int off = w * 64 + 2 * lane;
    const __nv_bfloat16* ob = g_eKVo + (size_t)b * OBS * 1024 + off;
    const __nv_bfloat16* rbp = g_eKV + (size_t)bm * HOR * 1024 + off;
    const int fr = f - OBS;
    for (int l = 0; l < OBS; l++) {
        float2 kf = __bfloat1622float2(*(const __nv_bfloat162*)(ob + l * 1024));
        float d = q0 * kf.x + q1 * kf.y;
#pragma unroll
        for (int o = 16; o; o >>= 1) d += __shfl_xor_sync(0xffffffffu, d, o);
        if (lane == 0) sp[w][l] = (d + qdot) * 0.125f;
    }
    for (int l = 0; l < fr; l++) {
        float2 kf = __bfloat1622float2(*(const __nv_bfloat162*)(rbp + l * 1024));
        float d = q0 * kf.x + q1 * kf.y;
#pragma unroll
        for (int o = 16; o; o >>= 1) d += __shfl_xor_sync(0xffffffffu, d, o);
        if (lane == 0) sp[w][OBS + l] = (d + qdot) * 0.125f;
    }
    __syncwarp();
    float mx = -1e30f;
    if (lane < f)      mx = sp[w][lane];
    if (lane + 32 < f) mx = fmaxf(mx, sp[w][lane + 32]);
#pragma unroll
    for (int o = 16; o; o >>= 1) mx = fmaxf(mx, __shfl_xor_sync(0xffffffffu, mx, o));
    float e0 = 0.f, e1 = 0.f;
    if (lane < f)      e0 = expf(sp[w][lane] - mx);
    if (lane + 32 < f) e1 = expf(sp[w][lane + 32] - mx);
    float sum = e0 + e1;
#pragma unroll
    for (int o = 16; o; o >>= 1) sum += __shfl_xor_sync(0xffffffffu, sum, o);
    if (lane < f)      sp[w][lane] = e0;
    if (lane + 32 < f) sp[w][lane + 32] = e1;
    __syncwarp();
    float inv = 1.f / sum;
    const float* cvp = qp + 1024;
    float a0 = 0.f, a1 = 0.f;
    for (int l = 0; l < OBS; l++) {
        float p = sp[w][l];
        float2 vf = __bfloat1622float2(*(const __nv_bfloat162*)(ob + 512 + l * 1024));
        a0 += p * vf.x; a1 += p * vf.y;
    }
    for (int l = 0; l < fr; l++) {
        float p = sp[w][OBS + l];
        float2 vf = __bfloat1622float2(*(const __nv_bfloat162*)(rbp + 512 + l * 1024));
        a0 += p * vf.x; a1 += p * vf.y;
    }
    float* op = g_ctx + (size_t)bm * 512 + off;
    *(float2*)op = make_float2(tfr(cvp[2 * lane] + a0 * inv),
                               tfr(cvp[2 * lane + 1] + a1 * inv));
}

// --------------- layernorm: warp per row, out = tf32(LN(x1+x2+x3)*g+b) ------------
__global__ void k_ln(const float* __restrict__ x1, const float* __restrict__ x2,
                     const float* __restrict__ x3,
                     const float* __restrict__ g, const float* __restrict__ bb,
                     float* __restrict__ out)
{
    int w = threadIdx.x >> 5, lane = threadIdx.x & 31;
    int row = blockIdx.x * 8 + w;
    size_t base = (size_t)row * 512;
    float v[16];
    float sum = 0.f;
#pragma unroll
    for (int j = 0; j < 16; j++) {
        int e = lane + j * 32;
        v[j] = x1[base + e] + x2[base + e] + x3[base + e];
        sum += v[j];
    }
#pragma unroll
    for (int o = 16; o; o >>= 1) sum += __shfl_xor_sync(0xffffffffu, sum, o);
    float mu = sum * (1.f / 512.f);
    float var = 0.f;
#pragma unroll
    for (int j = 0; j < 16; j++) { float d = v[j] - mu; var += d * d; }
#pragma unroll
    for (int o = 16; o; o >>= 1) var += __shfl_xor_sync(0xffffffffu, var, o);
    float rs = rsqrtf(var * (1.f / 512.f) + 1e-5f);
#pragma unroll
    for (int j = 0; j < 16; j++) {
        int e = lane + j * 32;
        out[base + e] = tfr((v[j] - mu) * rs * g[e] + bb[e]);
    }
}

// ---- fused per-step epilogue: out + emb + prep for step f+1 ---------------------
__global__ void k_step(const float* __restrict__ Wout, const float* __restrict__ bout,
                       const float* __restrict__ Wemb, const float* __restrict__ bemb,
                       const float* __restrict__ loc, const float* __restrict__ feat,
                       const float* __restrict__ Wfus,
                       float* __restrict__ dout, int f, int bm0)
{
    int bm = blockIdx.x + bm0, tid = threadIdx.x;
    int w = tid >> 5, lane = tid & 31;
    int b = bm & 255, m = bm >> 8;
    __shared__ float r0[4], r1[4];
    __shared__ float se[32], ex[32];

    float s0 = 0.f, s1 = 0.f;
    const float* fp  = g_fus  + (size_t)bm * 448;
    const float* fpb = g_fusb + (size_t)bm * 448;
    for (int c = tid; c < 448; c += 128) {
        float v = fp[c] + fpb[c];
        s0 += v * Wout[c * 2 + 0];
        s1 += v * Wout[c * 2 + 1];
    }
#pragma unroll
    for (int o = 16; o; o >>= 1) {
        s0 += __shfl_xor_sync(0xffffffffu, s0, o);
        s1 += __shfl_xor_sync(0xffffffffu, s1, o);
    }
    if (lane == 0) { r0[w] = s0; r1[w] = s1; }
    __syncthreads();
    float o0 = r0[0] + r0[1] + r0[2] + r0[3] + bout[0];
    float o1 = r1[0] + r1[1] + r1[2] + r1[3] + bout[1];

    if (tid < 32)
        se[tid] = fmaxf(o0 * Wemb[tid] + o1 * Wemb[32 + tid] + bemb[tid], 0.f);
    if (tid == 0) {
        int t = f - OBS;
        dout[b * (NM * HOR * 2) + m * (HOR * 2) + t * 2 + 0] = o0;
        dout[b * (NM * HOR * 2) + m * (HOR * 2) + t * 2 + 1] = o1;
    }
    __syncthreads();

    int fn = f + 1;
    if (fn < OBS + HOR) {
        float gx = loc[(b * NM + m) * 2 + 0], gy = loc[(b * NM + m) * 2 + 1];
        float dx = gx - o0, dy = gy - o1;
        float t = (float)fn;
        if (tid < 32) {
            float v;
            if (tid < 8)       v = (tid & 1) ? gy : gx;
            else if (tid < 16) v = (tid & 1) ? o1 : o0;
            else if (tid < 24) v = (tid & 1) ? dy : dx;
            else               v = t;
            ex[tid] = v;
            g_E[bm * 64 + tid] = tfr(v);
            g_E[bm * 64 + 32 + tid] = tfr(se[tid]);
        }
        __syncthreads();
        for (int c = tid; c < 512; c += 128) {
            float v;
            if (c < 32)      v = se[c];
            else if (c < 64) v = ex[c - 32];
            else             v = feat[b * INC + (c - 64)];
            g_xlast[bm * 512 + c] = v;
        }
        for (int c = tid; c < 448; c += 128) {
            float v = g_cffus[b * 448 + c];
            v += o0 * Wfus[(512 + 0) * 448 + c];
            v += o1 * Wfus[(512 + 1) * 448 + c];
            v += gx * Wfus[(512 + 2) * 448 + c];
            v += gy * Wfus[(512 + 3) * 448 + c];
            v += dx * Wfus[(512 + 4) * 448 + c];
            v += dy * Wfus[(512 + 5) * 448 + c];
            v += t  * Wfus[(512 + 6) * 448 + c];
            g_rowfus[bm * 448 + c] = v;
        }
    }
}

// ----------------------------------- launch ---------------------------------------
extern "C" void kernel_launch(void* const* d_in, const int* in_sizes, int n_in,
                              void* d_out, int out_size)
{
    const float* feat = (const float*)d_in[0];
    const float* loc  = (const float*)d_in[1];
    const float* obs  = (const float*)d_in[2];
    const float* Wemb = (const float*)d_in[3];
    const float* bemb = (const float*)d_in[4];
    const float* Wqkv = (const float*)d_in[5];
    const float* bqkv = (const float*)d_in[6];
    const float* Wo   = (const float*)d_in[7];
    const float* bo   = (const float*)d_in[8];
    const float* Wff1 = (const float*)d_in[9];
    const float* bff1 = (const float*)d_in[10];
    const float* Wff2 = (const float*)d_in[11];
    const float* bff2 = (const float*)d_in[12];
    const float* ln1g = (const float*)d_in[13];
    const float* ln1b = (const float*)d_in[14];
    const float* ln2g = (const float*)d_in[15];
    const float* ln2b = (const float*)d_in[16];
    const float* Wfus = (const float*)d_in[17];
    const float* bfus = (const float*)d_in[18];
    const float* Wout = (const float*)d_in[19];
    const float* bout = (const float*)d_in[20];
    float* outp = (float*)d_out;

    float *cfeat, *E, *xlast, *rowfus, *QKVC, *ctx, *wo, *wob, *h1, *ff1, *ff2,
          *ff2b, *h2, *fus, *fusb, *Wor, *Wff1r, *Wff2r, *Wfusr, *Wcat;
    __nv_bfloat16 *eKV;
    cudaGetSymbolAddress((void**)&cfeat,  g_cfeat);
    cudaGetSymbolAddress((void**)&Wcat,   g_Wcat);
    cudaGetSymbolAddress((void**)&Wor,    g_Wor);
    cudaGetSymbolAddress((void**)&Wff1r,  g_Wff1r);
    cudaGetSymbolAddress((void**)&Wff2r,  g_Wff2r);
    cudaGetSymbolAddress((void**)&Wfusr,  g_Wfusr);
    cudaGetSymbolAddress((void**)&eKV,    g_eKV);
    cudaGetSymbolAddress((void**)&E,      g_E);
    cudaGetSymbolAddress((void**)&xlast,  g_xlast);
    cudaGetSymbolAddress((void**)&rowfus, g_rowfus);
    cudaGetSymbolAddress((void**)&QKVC,   g_QKVC);
    cudaGetSymbolAddress((void**)&ctx,    g_ctx);
    cudaGetSymbolAddress((void**)&wo,     g_wo);
    cudaGetSymbolAddress((void**)&wob,    g_wob);
    cudaGetSymbolAddress((void**)&h1,     g_h1);
    cudaGetSymbolAddress((void**)&ff1,    g_ff1);
    cudaGetSymbolAddress((void**)&ff2,    g_ff2);
    cudaGetSymbolAddress((void**)&ff2b,   g_ff2b);
    cudaGetSymbolAddress((void**)&h2,     g_h2);
    cudaGetSymbolAddress((void**)&fus,    g_fus);
    cudaGetSymbolAddress((void**)&fusb,   g_fusb);

    const float* NUL = (const float*)0;
    float* FNUL = (float*)0;
    __nv_bfloat16* BNUL = (__nv_bfloat16*)0;

    const int SMEMT = 3 * (64 * 36 + 32 * 68) * 4;  // 53760
    cudaFuncSetAttribute(k_gemmt, cudaFuncAttributeMaxDynamicSharedMemorySize, SMEMT);

    static cudaStream_t gs[NGRP - 1];
    static cudaEvent_t  evFork, evJoin[NGRP - 1];
    static int s_init = 0;
    if (!s_init) {
        for (int i = 0; i < NGRP - 1; i++)
            cudaStreamCreateWithFlags(&gs[i], cudaStreamNonBlocking);
        cudaEventCreateWithFlags(&evFork, cudaEventDisableTiming);
        for (int i = 0; i < NGRP - 1; i++)
            cudaEventCreateWithFlags(&evJoin[i], cudaEventDisableTiming);
        s_init = 1;
    }

    // ---- setup (main stream) ----
    const int NSET = 64 * 2560 + 512 * 512 + 512 * 2048 + 2048 * 512 + 512 * 448
                   + OBS * NB * 32;
    k_setup<<<(NSET + 255) / 256, 256>>>(Wqkv, Wo, Wff1, Wff2, Wfus, obs, Wemb, bemb);
    k_gemms<<<dim3(24, 40, 3), 256>>>(feat, Wqkv, bqkv, Wfus, bfus);
    k_initprep<<<BMT, 128>>>(obs, Wemb, bemb, loc, feat, Wfus);

    cudaEventRecord(evFork, 0);
    for (int i = 0; i < NGRP - 1; i++) cudaStreamWaitEvent(gs[i], evFork, 0);

    const int EKLD = HOR * 1024;
    const int GY = GROWS / 64;   // 8
    for (int g = 0; g < NGRP; g++) {
        cudaStream_t st = (g == 0) ? (cudaStream_t)0 : gs[g - 1];
        const int off = g * GROWS;
        float* Eg   = E + (size_t)off * 64;
        float* Qg   = QKVC + (size_t)off * 1536;
        float* ctxg = ctx + (size_t)off * 512;
        float* wog  = wo + (size_t)off * 512;
        float* wobg = wob + (size_t)off * 512;
        float* xlg  = xlast + (size_t)off * 512;
        float* h1g  = h1 + (size_t)off * 512;
        float* ff1g = ff1 + (size_t)off * 2048;
        float* ff2g = ff2 + (size_t)off * 512;
        float* f2bg = ff2b + (size_t)off * 512;
        float* h2g  = h2 + (size_t)off * 512;
        float* fusg = fus + (size_t)off * 448;
        float* fubg = fusb + (size_t)off * 448;
        float* rfg  = rowfus + (size_t)off * 448;
        __nv_bfloat16* eKVg = eKV + (size_t)off * EKLD;

        for (int f = OBS; f < OBS + HOR; f++) {
            int ekoff = ((f == OBS) ? (HOR - 1) : (f - 1 - OBS)) * 1024;
            // QKVC + eKV (K=64)
            k_gemmt<<<dim3(40, GY), 256, SMEMT, st>>>(Eg, 64, Wcat, 2560, Qg, 1536, 64,
                                                      NUL, cfeat, 256, 1536, 0, 0, FNUL,
                                                      eKVg, 1536, ekoff, EKLD);
            k_attn<<<GROWS, 256, 0, st>>>(f, off);
            k_gemmt<<<dim3(8, GY, 2), 256, SMEMT, st>>>(ctxg, 512, Wor, 512, wog, 512, 256,
                                                        bo, NUL, 1, 0, 0, 0, wobg,
                                                        BNUL, 1 << 30, 0, 0);
            k_ln<<<GROWS / 8, 256, 0, st>>>(xlg, wog, wobg, ln1g, ln1b, h1g);
            k_gemmt<<<dim3(32, GY), 256, SMEMT, st>>>(h1g, 512, Wff1r, 2048, ff1g, 2048, 512,
                                                      bff1, NUL, 1, 0, 1, 1, FNUL,
                                                      BNUL, 1 << 30, 0, 0);
            k_gemmt<<<dim3(8, GY, 2), 256, SMEMT, st>>>(ff1g, 2048, Wff2r, 512, ff2g, 512, 1024,
                                                        bff2, NUL, 1, 0, 0, 0, f2bg,
                                                        BNUL, 1 << 30, 0, 0);
            k_ln<<<GROWS / 8, 256, 0, st>>>(h1g, ff2g, f2bg, ln2g, ln2b, h2g);
            k_gemmt<<<dim3(7, GY, 2), 256, SMEMT, st>>>(h2g, 512, Wfusr, 448, fusg, 448, 256,
                                                        NUL, rfg, GROWS, 448, 0, 0, fubg,
                                                        BNUL, 1 << 30, 0, 0);
            k_step<<<GROWS, 128, 0, st>>>(Wout, bout, Wemb, bemb, loc, feat, Wfus,
                                          outp, f, off);
        }
    }

    for (int i = 0; i < NGRP - 1; i++) {
        cudaEventRecord(evJoin[i], gs[i]);
        cudaStreamWaitEvent((cudaStream_t)0, evJoin[i], 0);
    }
    (void)in_sizes; (void)n_in; (void)out_size;
}